// round 1
// baseline (speedup 1.0000x reference)
#include <cuda_runtime.h>
#include <cuda_bf16.h>
#include <math.h>
#include <float.h>

// Problem constants
#define S 2048
#define H 2048
#define NH 16
#define D 128
#define E 8
#define TOPK 4
#define IE 1408
#define IS 5632

// ---------------- scratch (static device globals; no allocation) --------------
__device__ float g_h[S * H];
__device__ float g_q[S * H];
__device__ float g_k[S * H];
__device__ float g_v[S * H];
__device__ float g_scores[(size_t)NH * S * S]; // 256 MB
__device__ float g_attn[S * H];
__device__ float g_x1[S * H];
__device__ float g_h2[S * H];
__device__ float g_gb[S * IE];
__device__ float g_ub[S * IE];
__device__ float g_moe[S * H];
__device__ float g_sgb[S * IS];
__device__ float g_sub[S * IS];
__device__ float g_sdwn[S * H];
__device__ float g_wbuf[E * S];
__device__ float g_gatev[S];

// ---------------- RMSNorm ----------------
__global__ void rmsnorm_kernel(const float* __restrict__ x,
                               const float* __restrict__ w,
                               float* __restrict__ out) {
    const float* xr = x + (long long)blockIdx.x * H;
    float* orow = out + (long long)blockIdx.x * H;
    __shared__ float red[256];
    float s = 0.f;
    for (int j = threadIdx.x; j < H; j += 256) {
        float v = xr[j];
        s += v * v;
    }
    red[threadIdx.x] = s;
    __syncthreads();
    for (int st = 128; st > 0; st >>= 1) {
        if (threadIdx.x < st) red[threadIdx.x] += red[threadIdx.x + st];
        __syncthreads();
    }
    float inv = 1.0f / sqrtf(red[0] / (float)H + 1e-6f);
    for (int j = threadIdx.x; j < H; j += 256) orow[j] = w[j] * xr[j] * inv;
}

// ---------------- generic 128x128x8 SGEMM with epilogue flags ----------------
// C[M,N] = epilogue( A[M,K] @ B[K,N] )   (transB: B is [N,K] row-major)
// All M,N multiples of 128; K multiple of 8. blockIdx.z batches via strides.
__global__ __launch_bounds__(256, 2)
void sgemm_kernel(const float* __restrict__ A, int lda, long long sA,
                  const float* __restrict__ B, int ldb, long long sB,
                  float* __restrict__ C, int ldc, long long sC,
                  int K,
                  const float* __restrict__ bias,
                  const float* __restrict__ residual, int ldr,
                  const float* __restrict__ rowscale, int accMode,
                  int transB, int causal, float scale) {
    __shared__ __align__(16) float As[8][128];
    __shared__ __align__(16) float Bs[8][128];

    const int bz = blockIdx.z;
    A += (long long)bz * sA;
    B += (long long)bz * sB;
    C += (long long)bz * sC;

    const int row0 = blockIdx.y * 128;
    const int col0 = blockIdx.x * 128;
    const int tid = threadIdx.x;
    const int trow = (tid >> 4) * 8;  // 0..120
    const int tcol = (tid & 15) * 8;  // 0..120

    const int aRow = tid >> 1;       // 0..127
    const int aCol = (tid & 1) * 4;  // 0 or 4
    const int bRow = tid >> 5;       // 0..7
    const int bCol = (tid & 31) * 4; // 0..124

    float acc[8][8];
#pragma unroll
    for (int i = 0; i < 8; i++)
#pragma unroll
        for (int j = 0; j < 8; j++) acc[i][j] = 0.f;

    const float* Aptr = A + (long long)(row0 + aRow) * lda + aCol;
    const float* BptrNN = B + (long long)bRow * ldb + col0 + bCol;
    const float* BptrNT = B + (long long)(col0 + aRow) * ldb + aCol;

    for (int k0 = 0; k0 < K; k0 += 8) {
        float4 av = *reinterpret_cast<const float4*>(Aptr + k0);
        As[aCol + 0][aRow] = av.x;
        As[aCol + 1][aRow] = av.y;
        As[aCol + 2][aRow] = av.z;
        As[aCol + 3][aRow] = av.w;
        if (transB) {
            float4 bv = *reinterpret_cast<const float4*>(BptrNT + k0);
            Bs[aCol + 0][aRow] = bv.x;
            Bs[aCol + 1][aRow] = bv.y;
            Bs[aCol + 2][aRow] = bv.z;
            Bs[aCol + 3][aRow] = bv.w;
        } else {
            float4 bv = *reinterpret_cast<const float4*>(BptrNN + (long long)k0 * ldb);
            *reinterpret_cast<float4*>(&Bs[bRow][bCol]) = bv;
        }
        __syncthreads();
#pragma unroll
        for (int kk = 0; kk < 8; kk++) {
            float a[8], b[8];
            float4 a0 = *reinterpret_cast<const float4*>(&As[kk][trow]);
            float4 a1 = *reinterpret_cast<const float4*>(&As[kk][trow + 4]);
            float4 b0 = *reinterpret_cast<const float4*>(&Bs[kk][tcol]);
            float4 b1 = *reinterpret_cast<const float4*>(&Bs[kk][tcol + 4]);
            a[0] = a0.x; a[1] = a0.y; a[2] = a0.z; a[3] = a0.w;
            a[4] = a1.x; a[5] = a1.y; a[6] = a1.z; a[7] = a1.w;
            b[0] = b0.x; b[1] = b0.y; b[2] = b0.z; b[3] = b0.w;
            b[4] = b1.x; b[5] = b1.y; b[6] = b1.z; b[7] = b1.w;
#pragma unroll
            for (int i = 0; i < 8; i++)
#pragma unroll
                for (int j = 0; j < 8; j++) acc[i][j] += a[i] * b[j];
        }
        __syncthreads();
    }

#pragma unroll
    for (int i = 0; i < 8; i++) {
        int r = row0 + trow + i;
#pragma unroll
        for (int j = 0; j < 8; j++) {
            int c = col0 + tcol + j;
            float v = acc[i][j] * scale;
            if (causal && c > r) v = -3.4028234663852886e38f;
            if (bias) v += bias[c];
            if (residual) v += residual[(long long)r * ldr + c];
            long long idx = (long long)r * ldc + c;
            if (accMode == 1) C[idx] = rowscale[r] * v;
            else if (accMode == 2) C[idx] += rowscale[r] * v;
            else C[idx] = v;
        }
    }
}

// ---------------- RoPE ----------------
__global__ void rope_kernel(float* __restrict__ q, float* __restrict__ k) {
    int s = blockIdx.x;
    int h = blockIdx.y;
    int j = threadIdx.x; // 0..63
    double invd = pow(1.0e6, -(double)j / 64.0);
    float ang = (float)((double)s * invd);
    float c = cosf(ang), sn = sinf(ang);
    long long base = ((long long)s * NH + h) * D;
    float q1 = q[base + j], q2 = q[base + j + 64];
    q[base + j] = q1 * c - q2 * sn;
    q[base + j + 64] = q2 * c + q1 * sn;
    float k1 = k[base + j], k2 = k[base + j + 64];
    k[base + j] = k1 * c - k2 * sn;
    k[base + j + 64] = k2 * c + k1 * sn;
}

// ---------------- row softmax over scores ----------------
__global__ void softmax_kernel(float* __restrict__ scores) {
    float* row = scores + ((long long)blockIdx.y * S + blockIdx.x) * S;
    __shared__ float red[256];
    int tid = threadIdx.x;
    float m = -FLT_MAX;
    for (int j = tid; j < S; j += 256) m = fmaxf(m, row[j]);
    red[tid] = m;
    __syncthreads();
    for (int st = 128; st > 0; st >>= 1) {
        if (tid < st) red[tid] = fmaxf(red[tid], red[tid + st]);
        __syncthreads();
    }
    m = red[0];
    __syncthreads();
    float sum = 0.f;
    for (int j = tid; j < S; j += 256) {
        float e = expf(row[j] - m);
        row[j] = e;
        sum += e;
    }
    red[tid] = sum;
    __syncthreads();
    for (int st = 128; st > 0; st >>= 1) {
        if (tid < st) red[tid] += red[tid + st];
        __syncthreads();
    }
    float inv = 1.0f / red[0];
    for (int j = tid; j < S; j += 256) row[j] *= inv;
}

// ---------------- router: logits, softmax, top-4 -> per-expert weights -------
__global__ void router_kernel(const float* __restrict__ h2,
                              const float* __restrict__ gate_w,
                              float* __restrict__ logits_out,
                              float* __restrict__ wbuf) {
    int s = blockIdx.x;
    const float* hr = h2 + (long long)s * H;
    __shared__ float red[256][E];
    float p[E];
#pragma unroll
    for (int e = 0; e < E; e++) p[e] = 0.f;
    for (int j = threadIdx.x; j < H; j += 256) {
        float hv = hr[j];
#pragma unroll
        for (int e = 0; e < E; e++) p[e] += hv * gate_w[j * E + e];
    }
#pragma unroll
    for (int e = 0; e < E; e++) red[threadIdx.x][e] = p[e];
    __syncthreads();
    for (int st = 128; st > 0; st >>= 1) {
        if (threadIdx.x < st)
#pragma unroll
            for (int e = 0; e < E; e++) red[threadIdx.x][e] += red[threadIdx.x + st][e];
        __syncthreads();
    }
    if (threadIdx.x == 0) {
        float logit[E];
        float m = -FLT_MAX;
#pragma unroll
        for (int e = 0; e < E; e++) {
            logit[e] = red[0][e];
            logits_out[(long long)s * E + e] = logit[e];
            m = fmaxf(m, logit[e]);
        }
        float sum = 0.f, rw[E];
#pragma unroll
        for (int e = 0; e < E; e++) {
            rw[e] = expf(logit[e] - m);
            sum += rw[e];
        }
        float inv = 1.0f / sum;
#pragma unroll
        for (int e = 0; e < E; e++) rw[e] *= inv;
        float wsel[E];
        bool used[E];
#pragma unroll
        for (int e = 0; e < E; e++) { wsel[e] = 0.f; used[e] = false; }
        for (int k = 0; k < TOPK; k++) {
            int best = -1;
            float bv = -FLT_MAX;
            for (int e = 0; e < E; e++)
                if (!used[e] && rw[e] > bv) { bv = rw[e]; best = e; }
            used[best] = true;
            wsel[best] = bv;
        }
#pragma unroll
        for (int e = 0; e < E; e++) wbuf[e * S + s] = wsel[e];
    }
}

// ---------------- h2 . sgate (per token scalar) ----------------
__global__ void rowdot_kernel(const float* __restrict__ h2,
                              const float* __restrict__ sgate,
                              float* __restrict__ gatev) {
    int s = blockIdx.x;
    const float* hr = h2 + (long long)s * H;
    __shared__ float red[256];
    float acc = 0.f;
    for (int j = threadIdx.x; j < H; j += 256) acc += hr[j] * sgate[j];
    red[threadIdx.x] = acc;
    __syncthreads();
    for (int st = 128; st > 0; st >>= 1) {
        if (threadIdx.x < st) red[threadIdx.x] += red[threadIdx.x + st];
        __syncthreads();
    }
    if (threadIdx.x == 0) gatev[s] = red[0];
}

// ---------------- elementwise silu(g)*u, in place into g ----------------
__global__ void silu_mul_kernel(float* __restrict__ g, const float* __restrict__ u,
                                long long n) {
    long long i = (long long)blockIdx.x * 256 + threadIdx.x;
    if (i < n) {
        float x = g[i];
        float sg = 1.0f / (1.0f + expf(-x));
        g[i] = x * sg * u[i];
    }
}

// ---------------- final combine ----------------
__global__ void final_kernel(const float* __restrict__ x1,
                             const float* __restrict__ moe,
                             const float* __restrict__ sdwn,
                             const float* __restrict__ gatev,
                             float* __restrict__ out) {
    long long i = (long long)blockIdx.x * 256 + threadIdx.x;
    int srow = (int)(i / H);
    float gv = 1.0f / (1.0f + expf(-gatev[srow]));
    out[i] = x1[i] + moe[i] + gv * sdwn[i];
}

// ---------------- host ----------------
static void launch_gemm(const float* A, int lda, long long sA,
                        const float* B, int ldb, long long sB,
                        float* C, int ldc, long long sC,
                        int M, int N, int K, int batch,
                        const float* bias, const float* res, int ldr,
                        const float* rs, int accMode, int transB, int causal,
                        float scale) {
    dim3 grid(N / 128, M / 128, batch);
    sgemm_kernel<<<grid, 256>>>(A, lda, sA, B, ldb, sB, C, ldc, sC, K,
                                bias, res, ldr, rs, accMode, transB, causal, scale);
}

extern "C" void kernel_launch(void* const* d_in, const int* in_sizes, int n_in,
                              void* d_out, int out_size) {
    (void)in_sizes; (void)n_in; (void)out_size;
    const float* x     = (const float*)d_in[0];
    const float* ln1   = (const float*)d_in[1];
    const float* ln2   = (const float*)d_in[2];
    const float* wq    = (const float*)d_in[3];
    const float* bq    = (const float*)d_in[4];
    const float* wk    = (const float*)d_in[5];
    const float* bk    = (const float*)d_in[6];
    const float* wv    = (const float*)d_in[7];
    const float* bv    = (const float*)d_in[8];
    const float* wo    = (const float*)d_in[9];
    const float* gatew = (const float*)d_in[10];
    const float* eg    = (const float*)d_in[11];
    const float* eu    = (const float*)d_in[12];
    const float* ed    = (const float*)d_in[13];
    const float* sg    = (const float*)d_in[14];
    const float* su    = (const float*)d_in[15];
    const float* sd    = (const float*)d_in[16];
    const float* sgate = (const float*)d_in[17];
    float* out = (float*)d_out;

    float *h, *q, *k, *v, *scores, *attn, *x1, *h2, *gb, *ub, *moe, *sgb, *sub,
        *sdwn, *wbuf, *gatev;
    cudaGetSymbolAddress((void**)&h, g_h);
    cudaGetSymbolAddress((void**)&q, g_q);
    cudaGetSymbolAddress((void**)&k, g_k);
    cudaGetSymbolAddress((void**)&v, g_v);
    cudaGetSymbolAddress((void**)&scores, g_scores);
    cudaGetSymbolAddress((void**)&attn, g_attn);
    cudaGetSymbolAddress((void**)&x1, g_x1);
    cudaGetSymbolAddress((void**)&h2, g_h2);
    cudaGetSymbolAddress((void**)&gb, g_gb);
    cudaGetSymbolAddress((void**)&ub, g_ub);
    cudaGetSymbolAddress((void**)&moe, g_moe);
    cudaGetSymbolAddress((void**)&sgb, g_sgb);
    cudaGetSymbolAddress((void**)&sub, g_sub);
    cudaGetSymbolAddress((void**)&sdwn, g_sdwn);
    cudaGetSymbolAddress((void**)&wbuf, g_wbuf);
    cudaGetSymbolAddress((void**)&gatev, g_gatev);

    const float ascale = 0.08838834764831845f; // 1/sqrt(128)

    // 1. h = rmsnorm(x, ln1)
    rmsnorm_kernel<<<S, 256>>>(x, ln1, h);

    // 2. q,k,v = h@W + b
    launch_gemm(h, H, 0, wq, NH * D, 0, q, NH * D, 0, S, NH * D, H, 1, bq,
                nullptr, 0, nullptr, 0, 0, 0, 1.0f);
    launch_gemm(h, H, 0, wk, NH * D, 0, k, NH * D, 0, S, NH * D, H, 1, bk,
                nullptr, 0, nullptr, 0, 0, 0, 1.0f);
    launch_gemm(h, H, 0, wv, NH * D, 0, v, NH * D, 0, S, NH * D, H, 1, bv,
                nullptr, 0, nullptr, 0, 0, 0, 1.0f);

    // 3. RoPE
    rope_kernel<<<dim3(S, NH), 64>>>(q, k);

    // 4. scores = causal( q @ k^T * scale )   batched over heads
    launch_gemm(q, NH * D, D, k, NH * D, D, scores, S, (long long)S * S,
                S, S, D, NH, nullptr, nullptr, 0, nullptr, 0, 1, 1, ascale);

    // 5. softmax rows
    softmax_kernel<<<dim3(S, NH), 256>>>(scores);

    // 6. attn = probs @ v  batched over heads
    launch_gemm(scores, S, (long long)S * S, v, NH * D, D, attn, NH * D, D,
                S, D, S, NH, nullptr, nullptr, 0, nullptr, 0, 0, 0, 1.0f);

    // 7. x1 = x + attn @ wo
    launch_gemm(attn, NH * D, 0, wo, H, 0, x1, H, 0, S, H, NH * D, 1, nullptr,
                x, H, nullptr, 0, 0, 0, 1.0f);

    // 8. h2 = rmsnorm(x1, ln2)
    rmsnorm_kernel<<<S, 256>>>(x1, ln2, h2);

    // 9. router (writes logits to out tail + per-expert weights)
    router_kernel<<<S, 256>>>(h2, gatew, out + (long long)S * H, wbuf);

    // 10. dense MoE: for each expert, gup = silu(h2@eg)*(h2@eu); moe (+)= w_e * gup@ed
    for (int e = 0; e < E; e++) {
        const float* ege = eg + (long long)e * H * IE;
        const float* eue = eu + (long long)e * H * IE;
        const float* ede = ed + (long long)e * IE * H;
        launch_gemm(h2, H, 0, ege, IE, 0, gb, IE, 0, S, IE, H, 1, nullptr,
                    nullptr, 0, nullptr, 0, 0, 0, 1.0f);
        launch_gemm(h2, H, 0, eue, IE, 0, ub, IE, 0, S, IE, H, 1, nullptr,
                    nullptr, 0, nullptr, 0, 0, 0, 1.0f);
        long long n = (long long)S * IE;
        silu_mul_kernel<<<(unsigned)((n + 255) / 256), 256>>>(gb, ub, n);
        launch_gemm(gb, IE, 0, ede, H, 0, moe, H, 0, S, H, IE, 1, nullptr,
                    nullptr, 0, wbuf + e * S, e == 0 ? 1 : 2, 0, 0, 1.0f);
    }

    // 11. shared expert
    launch_gemm(h2, H, 0, sg, IS, 0, sgb, IS, 0, S, IS, H, 1, nullptr, nullptr,
                0, nullptr, 0, 0, 0, 1.0f);
    launch_gemm(h2, H, 0, su, IS, 0, sub, IS, 0, S, IS, H, 1, nullptr, nullptr,
                0, nullptr, 0, 0, 0, 1.0f);
    {
        long long n = (long long)S * IS;
        silu_mul_kernel<<<(unsigned)((n + 255) / 256), 256>>>(sgb, sub, n);
    }
    launch_gemm(sgb, IS, 0, sd, H, 0, sdwn, H, 0, S, H, IS, 1, nullptr, nullptr,
                0, nullptr, 0, 0, 0, 1.0f);

    // 12. gate scalar per token
    rowdot_kernel<<<S, 256>>>(h2, sgate, gatev);

    // 13. out = x1 + moe + sigmoid(gatev)*sdwn
    final_kernel<<<(S * H) / 256, 256>>>(x1, moe, sdwn, gatev, out);
}

// round 2
// speedup vs baseline: 1.2197x; 1.2197x over previous
#include <cuda_runtime.h>
#include <cuda_bf16.h>
#include <math.h>
#include <float.h>

#define S 2048
#define H 2048
#define NH 16
#define D 128
#define E 8
#define TOPK 4
#define IE 1408
#define IS 5632

// ---------------- scratch (static device globals; no allocation) --------------
__device__ float g_h[S * H];
__device__ float g_q[S * H];
__device__ float g_k[S * H];
__device__ float g_v[S * H];
__device__ float g_scores[(size_t)NH * S * S];
__device__ float g_attn[S * H];
__device__ float g_x1[S * H];
__device__ float g_h2[S * H];
__device__ float g_gb[S * IE];
__device__ float g_ub[S * IE];
__device__ float g_moe[S * H];
__device__ float g_sgb[S * IS];
__device__ float g_sub[S * IS];
__device__ float g_sdwn[S * H];
__device__ float g_wbuf[E * S];
__device__ float g_gatev[S];
__device__ int g_idx[E * S];
__device__ int g_cnt[E];

// ---------------- RMSNorm ----------------
__global__ void rmsnorm_kernel(const float* __restrict__ x,
                               const float* __restrict__ w,
                               float* __restrict__ out) {
    const float* xr = x + (long long)blockIdx.x * H;
    float* orow = out + (long long)blockIdx.x * H;
    __shared__ float red[256];
    float s = 0.f;
    for (int j = threadIdx.x; j < H; j += 256) {
        float v = xr[j];
        s += v * v;
    }
    red[threadIdx.x] = s;
    __syncthreads();
    for (int st = 128; st > 0; st >>= 1) {
        if (threadIdx.x < st) red[threadIdx.x] += red[threadIdx.x + st];
        __syncthreads();
    }
    float inv = 1.0f / sqrtf(red[0] / (float)H + 1e-6f);
    for (int j = threadIdx.x; j < H; j += 256) orow[j] = w[j] * xr[j] * inv;
}

// ---------------- 128x128x8 SGEMM, FFMA2 (fma.rn.f32x2) inner loop ------------
// C[M,N] = epilogue( A[M,K] @ B[K,N] ).  transB: B is [N,K] row-major.
// Optional: gatherA (A row = gidx[row]), cntPtr (dynamic M bound),
// accMode 0 = store, 3 = scatter-add C[gidx[r]] += rowscale[gidx[r]]*v,
// causal (skip upper blocks), kLimit (K bounded at row-block diagonal).
__global__ __launch_bounds__(256, 2)
void sgemm_kernel(const float* __restrict__ A, int lda, long long sA,
                  const float* __restrict__ B, int ldb, long long sB,
                  float* __restrict__ C, int ldc, long long sC,
                  int K,
                  const float* __restrict__ bias,
                  const float* __restrict__ residual, int ldr,
                  const float* __restrict__ rowscale,
                  const int* __restrict__ gidx,
                  const int* __restrict__ cntPtr,
                  int accMode, int gatherA, int transB, int causal, int kLimit,
                  float scale) {
    __shared__ __align__(16) float As[2][8][128];
    __shared__ __align__(16) float Bs[2][8][128];

    const int bz = blockIdx.z;
    A += (long long)bz * sA;
    B += (long long)bz * sB;
    C += (long long)bz * sC;

    const int row0 = blockIdx.y * 128;
    const int col0 = blockIdx.x * 128;
    if (causal && col0 > row0) return;
    const int cntV = cntPtr ? *cntPtr : (1 << 30);
    if (row0 >= cntV) return;
    int Keff = kLimit ? min(K, row0 + 128) : K;

    const int tid = threadIdx.x;
    const int trow = (tid >> 4) * 8;  // 0..120
    const int tcol = (tid & 15) * 8;  // 0..120

    const int aRow = tid >> 1;        // 0..127
    const int aCol = (tid & 1) * 4;   // 0 or 4
    const int bRow = tid >> 5;        // 0..7
    const int bCol = (tid & 31) * 4;  // 0..124

    // A load pointer (with optional gather)
    const float* Aptr;
    {
        int arow = row0 + aRow;
        if (gatherA) {
            int t = (arow < cntV) ? gidx[arow] : 0;
            t = min(max(t, 0), S - 1);
            Aptr = A + (long long)t * lda + aCol;
        } else {
            Aptr = A + (long long)arow * lda + aCol;
        }
    }
    const float* BptrNN = B + (long long)bRow * ldb + col0 + bCol;
    const float* BptrNT = B + (long long)(col0 + aRow) * ldb + aCol;

    unsigned long long acc[4][8];
#pragma unroll
    for (int i = 0; i < 4; i++)
#pragma unroll
        for (int j = 0; j < 8; j++) acc[i][j] = 0ull;

    // preload tile 0
    float4 av = *reinterpret_cast<const float4*>(Aptr);
    float4 bv = transB ? *reinterpret_cast<const float4*>(BptrNT)
                       : *reinterpret_cast<const float4*>(BptrNN);
    {
        As[0][aCol + 0][aRow] = av.x;
        As[0][aCol + 1][aRow] = av.y;
        As[0][aCol + 2][aRow] = av.z;
        As[0][aCol + 3][aRow] = av.w;
        if (transB) {
            Bs[0][aCol + 0][aRow] = bv.x;
            Bs[0][aCol + 1][aRow] = bv.y;
            Bs[0][aCol + 2][aRow] = bv.z;
            Bs[0][aCol + 3][aRow] = bv.w;
        } else {
            *reinterpret_cast<float4*>(&Bs[0][bRow][bCol]) = bv;
        }
    }
    __syncthreads();

    int buf = 0;
    for (int k0 = 0; k0 < Keff; k0 += 8) {
        const bool more = (k0 + 8) < Keff;
        if (more) {
            av = *reinterpret_cast<const float4*>(Aptr + k0 + 8);
            bv = transB
                     ? *reinterpret_cast<const float4*>(BptrNT + k0 + 8)
                     : *reinterpret_cast<const float4*>(BptrNN + (long long)(k0 + 8) * ldb);
        }
#pragma unroll
        for (int kk = 0; kk < 8; kk++) {
            ulonglong2 a01 = *reinterpret_cast<const ulonglong2*>(&As[buf][kk][trow]);
            ulonglong2 a23 = *reinterpret_cast<const ulonglong2*>(&As[buf][kk][trow + 4]);
            float4 b0 = *reinterpret_cast<const float4*>(&Bs[buf][kk][tcol]);
            float4 b1 = *reinterpret_cast<const float4*>(&Bs[buf][kk][tcol + 4]);
            unsigned long long ap[4];
            ap[0] = a01.x; ap[1] = a01.y; ap[2] = a23.x; ap[3] = a23.y;
            float bvals[8];
            bvals[0] = b0.x; bvals[1] = b0.y; bvals[2] = b0.z; bvals[3] = b0.w;
            bvals[4] = b1.x; bvals[5] = b1.y; bvals[6] = b1.z; bvals[7] = b1.w;
#pragma unroll
            for (int j = 0; j < 8; j++) {
                unsigned long long bp;
                asm("mov.b64 %0, {%1, %1};" : "=l"(bp) : "f"(bvals[j]));
#pragma unroll
                for (int i2 = 0; i2 < 4; i2++) {
                    asm("fma.rn.f32x2 %0, %1, %2, %0;"
                        : "+l"(acc[i2][j])
                        : "l"(ap[i2]), "l"(bp));
                }
            }
        }
        if (more) {
            int nb = buf ^ 1;
            As[nb][aCol + 0][aRow] = av.x;
            As[nb][aCol + 1][aRow] = av.y;
            As[nb][aCol + 2][aRow] = av.z;
            As[nb][aCol + 3][aRow] = av.w;
            if (transB) {
                Bs[nb][aCol + 0][aRow] = bv.x;
                Bs[nb][aCol + 1][aRow] = bv.y;
                Bs[nb][aCol + 2][aRow] = bv.z;
                Bs[nb][aCol + 3][aRow] = bv.w;
            } else {
                *reinterpret_cast<float4*>(&Bs[nb][bRow][bCol]) = bv;
            }
        }
        __syncthreads();
        buf ^= 1;
    }

    // epilogue
#pragma unroll
    for (int i2 = 0; i2 < 4; i2++) {
#pragma unroll
        for (int j = 0; j < 8; j++) {
            float lo, hi;
            asm("mov.b64 {%0, %1}, %2;" : "=f"(lo), "=f"(hi) : "l"(acc[i2][j]));
            int c = col0 + tcol + j;
#pragma unroll
            for (int half = 0; half < 2; half++) {
                int r = row0 + trow + 2 * i2 + half;
                if (r >= cntV) continue;
                float v = (half == 0 ? lo : hi) * scale;
                if (bias) v += bias[c];
                if (residual) v += residual[(long long)r * ldr + c];
                if (accMode == 3) {
                    int t = gidx[r];
                    C[(long long)t * ldc + c] += rowscale[t] * v;
                } else {
                    C[(long long)r * ldc + c] = v;
                }
            }
        }
    }
}

// ---------------- RoPE ----------------
__global__ void rope_kernel(float* __restrict__ q, float* __restrict__ k) {
    int s = blockIdx.x;
    int h = blockIdx.y;
    int j = threadIdx.x; // 0..63
    double invd = pow(1.0e6, -(double)j / 64.0);
    float ang = (float)((double)s * invd);
    float c = cosf(ang), sn = sinf(ang);
    long long base = ((long long)s * NH + h) * D;
    float q1 = q[base + j], q2 = q[base + j + 64];
    q[base + j] = q1 * c - q2 * sn;
    q[base + j + 64] = q2 * c + q1 * sn;
    float k1 = k[base + j], k2 = k[base + j + 64];
    k[base + j] = k1 * c - k2 * sn;
    k[base + j + 64] = k2 * c + k1 * sn;
}

// ---------------- causal row softmax (reads j<=r, zeros (r, blockEnd)) -------
__global__ void softmax_kernel(float* __restrict__ scores) {
    int r = blockIdx.x;
    float* row = scores + ((long long)blockIdx.y * S + r) * S;
    const int limit = r + 1;
    const int rBlk = ((r >> 7) + 1) << 7;
    __shared__ float red[256];
    int tid = threadIdx.x;
    float m = -FLT_MAX;
    for (int j = tid; j < limit; j += 256) m = fmaxf(m, row[j]);
    red[tid] = m;
    __syncthreads();
    for (int st = 128; st > 0; st >>= 1) {
        if (tid < st) red[tid] = fmaxf(red[tid], red[tid + st]);
        __syncthreads();
    }
    m = red[0];
    __syncthreads();
    float sum = 0.f;
    for (int j = tid; j < limit; j += 256) {
        float e = expf(row[j] - m);
        row[j] = e;
        sum += e;
    }
    red[tid] = sum;
    __syncthreads();
    for (int st = 128; st > 0; st >>= 1) {
        if (tid < st) red[tid] += red[tid + st];
        __syncthreads();
    }
    float inv = 1.0f / red[0];
    for (int j = tid; j < limit; j += 256) row[j] *= inv;
    for (int j = limit + tid; j < rBlk; j += 256) row[j] = 0.f;
}

// ---------------- router: logits, softmax, top-4, gather lists ---------------
__global__ void router_kernel(const float* __restrict__ h2,
                              const float* __restrict__ gate_w,
                              float* __restrict__ logits_out,
                              float* __restrict__ wbuf,
                              int* __restrict__ idxbuf,
                              int* __restrict__ cnt) {
    int s = blockIdx.x;
    const float* hr = h2 + (long long)s * H;
    __shared__ float red[256][E];
    float p[E];
#pragma unroll
    for (int e = 0; e < E; e++) p[e] = 0.f;
    for (int j = threadIdx.x; j < H; j += 256) {
        float hv = hr[j];
#pragma unroll
        for (int e = 0; e < E; e++) p[e] += hv * gate_w[j * E + e];
    }
#pragma unroll
    for (int e = 0; e < E; e++) red[threadIdx.x][e] = p[e];
    __syncthreads();
    for (int st = 128; st > 0; st >>= 1) {
        if (threadIdx.x < st)
#pragma unroll
            for (int e = 0; e < E; e++) red[threadIdx.x][e] += red[threadIdx.x + st][e];
        __syncthreads();
    }
    if (threadIdx.x == 0) {
        float logit[E];
        float m = -FLT_MAX;
#pragma unroll
        for (int e = 0; e < E; e++) {
            logit[e] = red[0][e];
            logits_out[(long long)s * E + e] = logit[e];
            m = fmaxf(m, logit[e]);
        }
        float sum = 0.f, rw[E];
#pragma unroll
        for (int e = 0; e < E; e++) {
            rw[e] = expf(logit[e] - m);
            sum += rw[e];
        }
        float inv = 1.0f / sum;
#pragma unroll
        for (int e = 0; e < E; e++) rw[e] *= inv;
        float wsel[E];
        bool used[E];
#pragma unroll
        for (int e = 0; e < E; e++) { wsel[e] = 0.f; used[e] = false; }
        for (int k = 0; k < TOPK; k++) {
            int best = -1;
            float bv = -FLT_MAX;
            for (int e = 0; e < E; e++)
                if (!used[e] && rw[e] > bv) { bv = rw[e]; best = e; }
            used[best] = true;
            wsel[best] = bv;
        }
#pragma unroll
        for (int e = 0; e < E; e++) {
            wbuf[e * S + s] = wsel[e];
            if (wsel[e] > 0.f) {
                int pos = atomicAdd(&cnt[e], 1);
                idxbuf[e * S + pos] = s;
            }
        }
    }
}

// ---------------- h2 . sgate (per token scalar) ----------------
__global__ void rowdot_kernel(const float* __restrict__ h2,
                              const float* __restrict__ sgate,
                              float* __restrict__ gatev) {
    int s = blockIdx.x;
    const float* hr = h2 + (long long)s * H;
    __shared__ float red[256];
    float acc = 0.f;
    for (int j = threadIdx.x; j < H; j += 256) acc += hr[j] * sgate[j];
    red[threadIdx.x] = acc;
    __syncthreads();
    for (int st = 128; st > 0; st >>= 1) {
        if (threadIdx.x < st) red[threadIdx.x] += red[threadIdx.x + st];
        __syncthreads();
    }
    if (threadIdx.x == 0) gatev[s] = red[0];
}

// ---------------- elementwise silu(g)*u ----------------
__global__ void silu_mul_kernel(float* __restrict__ g, const float* __restrict__ u,
                                long long n) {
    long long i = (long long)blockIdx.x * 256 + threadIdx.x;
    if (i < n) {
        float x = g[i];
        float sg = 1.0f / (1.0f + expf(-x));
        g[i] = x * sg * u[i];
    }
}

// ---------------- final combine ----------------
__global__ void final_kernel(const float* __restrict__ x1,
                             const float* __restrict__ moe,
                             const float* __restrict__ sdwn,
                             const float* __restrict__ gatev,
                             float* __restrict__ out) {
    long long i = (long long)blockIdx.x * 256 + threadIdx.x;
    int srow = (int)(i / H);
    float gv = 1.0f / (1.0f + expf(-gatev[srow]));
    out[i] = x1[i] + moe[i] + gv * sdwn[i];
}

// ---------------- host ----------------
static void launch_gemm(const float* A, int lda, long long sA,
                        const float* B, int ldb, long long sB,
                        float* C, int ldc, long long sC,
                        int M, int N, int K, int batch,
                        const float* bias, const float* res, int ldr,
                        const float* rs, const int* gidx, const int* cnt,
                        int accMode, int gatherA, int transB, int causal,
                        int kLimit, float scale) {
    dim3 grid(N / 128, M / 128, batch);
    sgemm_kernel<<<grid, 256>>>(A, lda, sA, B, ldb, sB, C, ldc, sC, K,
                                bias, res, ldr, rs, gidx, cnt, accMode,
                                gatherA, transB, causal, kLimit, scale);
}

extern "C" void kernel_launch(void* const* d_in, const int* in_sizes, int n_in,
                              void* d_out, int out_size) {
    (void)in_sizes; (void)n_in; (void)out_size;
    const float* x     = (const float*)d_in[0];
    const float* ln1   = (const float*)d_in[1];
    const float* ln2   = (const float*)d_in[2];
    const float* wq    = (const float*)d_in[3];
    const float* bq    = (const float*)d_in[4];
    const float* wk    = (const float*)d_in[5];
    const float* bk    = (const float*)d_in[6];
    const float* wv    = (const float*)d_in[7];
    const float* bv    = (const float*)d_in[8];
    const float* wo    = (const float*)d_in[9];
    const float* gatew = (const float*)d_in[10];
    const float* eg    = (const float*)d_in[11];
    const float* eu    = (const float*)d_in[12];
    const float* ed    = (const float*)d_in[13];
    const float* sg    = (const float*)d_in[14];
    const float* su    = (const float*)d_in[15];
    const float* sd    = (const float*)d_in[16];
    const float* sgate = (const float*)d_in[17];
    float* out = (float*)d_out;

    float *h, *q, *k, *v, *scores, *attn, *x1, *h2, *gb, *ub, *moe, *sgb, *sub,
        *sdwn, *wbuf, *gatev;
    int *idx, *cnt;
    cudaGetSymbolAddress((void**)&h, g_h);
    cudaGetSymbolAddress((void**)&q, g_q);
    cudaGetSymbolAddress((void**)&k, g_k);
    cudaGetSymbolAddress((void**)&v, g_v);
    cudaGetSymbolAddress((void**)&scores, g_scores);
    cudaGetSymbolAddress((void**)&attn, g_attn);
    cudaGetSymbolAddress((void**)&x1, g_x1);
    cudaGetSymbolAddress((void**)&h2, g_h2);
    cudaGetSymbolAddress((void**)&gb, g_gb);
    cudaGetSymbolAddress((void**)&ub, g_ub);
    cudaGetSymbolAddress((void**)&moe, g_moe);
    cudaGetSymbolAddress((void**)&sgb, g_sgb);
    cudaGetSymbolAddress((void**)&sub, g_sub);
    cudaGetSymbolAddress((void**)&sdwn, g_sdwn);
    cudaGetSymbolAddress((void**)&wbuf, g_wbuf);
    cudaGetSymbolAddress((void**)&gatev, g_gatev);
    cudaGetSymbolAddress((void**)&idx, g_idx);
    cudaGetSymbolAddress((void**)&cnt, g_cnt);

    const float ascale = 0.08838834764831845f; // 1/sqrt(128)

    // 1. h = rmsnorm(x, ln1)
    rmsnorm_kernel<<<S, 256>>>(x, ln1, h);

    // 2. q,k,v = h@W + b
    launch_gemm(h, H, 0, wq, NH * D, 0, q, NH * D, 0, S, NH * D, H, 1, bq,
                nullptr, 0, nullptr, nullptr, nullptr, 0, 0, 0, 0, 0, 1.0f);
    launch_gemm(h, H, 0, wk, NH * D, 0, k, NH * D, 0, S, NH * D, H, 1, bk,
                nullptr, 0, nullptr, nullptr, nullptr, 0, 0, 0, 0, 0, 1.0f);
    launch_gemm(h, H, 0, wv, NH * D, 0, v, NH * D, 0, S, NH * D, H, 1, bv,
                nullptr, 0, nullptr, nullptr, nullptr, 0, 0, 0, 0, 0, 1.0f);

    // 3. RoPE
    rope_kernel<<<dim3(S, NH), 64>>>(q, k);

    // 4. scores = q @ k^T * scale (lower-triangular blocks only)
    launch_gemm(q, NH * D, D, k, NH * D, D, scores, S, (long long)S * S,
                S, S, D, NH, nullptr, nullptr, 0, nullptr, nullptr, nullptr,
                0, 0, 1, 1, 0, ascale);

    // 5. causal softmax
    softmax_kernel<<<dim3(S, NH), 256>>>(scores);

    // 6. attn = probs @ v (K bounded at diagonal block)
    launch_gemm(scores, S, (long long)S * S, v, NH * D, D, attn, NH * D, D,
                S, D, S, NH, nullptr, nullptr, 0, nullptr, nullptr, nullptr,
                0, 0, 0, 0, 1, 1.0f);

    // 7. x1 = x + attn @ wo
    launch_gemm(attn, NH * D, 0, wo, H, 0, x1, H, 0, S, H, NH * D, 1, nullptr,
                x, H, nullptr, nullptr, nullptr, 0, 0, 0, 0, 0, 1.0f);

    // 8. h2 = rmsnorm(x1, ln2)
    rmsnorm_kernel<<<S, 256>>>(x1, ln2, h2);

    // 9. router (logits to out tail, weights, gather lists)
    cudaMemsetAsync(cnt, 0, E * sizeof(int));
    router_kernel<<<S, 256>>>(h2, gatew, out + (long long)S * H, wbuf, idx, cnt);

    // 10. sparse MoE: per expert, only gathered tokens
    cudaMemsetAsync(moe, 0, (size_t)S * H * sizeof(float));
    for (int e = 0; e < E; e++) {
        const float* ege = eg + (long long)e * H * IE;
        const float* eue = eu + (long long)e * H * IE;
        const float* ede = ed + (long long)e * IE * H;
        launch_gemm(h2, H, 0, ege, IE, 0, gb, IE, 0, S, IE, H, 1, nullptr,
                    nullptr, 0, nullptr, idx + e * S, cnt + e, 0, 1, 0, 0, 0, 1.0f);
        launch_gemm(h2, H, 0, eue, IE, 0, ub, IE, 0, S, IE, H, 1, nullptr,
                    nullptr, 0, nullptr, idx + e * S, cnt + e, 0, 1, 0, 0, 0, 1.0f);
        long long n = (long long)S * IE;
        silu_mul_kernel<<<(unsigned)((n + 255) / 256), 256>>>(gb, ub, n);
        launch_gemm(gb, IE, 0, ede, H, 0, moe, H, 0, S, H, IE, 1, nullptr,
                    nullptr, 0, wbuf + e * S, idx + e * S, cnt + e, 3, 0, 0, 0, 0, 1.0f);
    }

    // 11. shared expert
    launch_gemm(h2, H, 0, sg, IS, 0, sgb, IS, 0, S, IS, H, 1, nullptr, nullptr,
                0, nullptr, nullptr, nullptr, 0, 0, 0, 0, 0, 1.0f);
    launch_gemm(h2, H, 0, su, IS, 0, sub, IS, 0, S, IS, H, 1, nullptr, nullptr,
                0, nullptr, nullptr, nullptr, 0, 0, 0, 0, 0, 1.0f);
    {
        long long n = (long long)S * IS;
        silu_mul_kernel<<<(unsigned)((n + 255) / 256), 256>>>(sgb, sub, n);
    }
    launch_gemm(sgb, IS, 0, sd, H, 0, sdwn, H, 0, S, H, IS, 1, nullptr, nullptr,
                0, nullptr, nullptr, nullptr, 0, 0, 0, 0, 0, 1.0f);

    // 12. gate scalar per token
    rowdot_kernel<<<S, 256>>>(h2, sgate, gatev);

    // 13. out = x1 + moe + sigmoid(gatev)*sdwn
    final_kernel<<<(S * H) / 256, 256>>>(x1, moe, sdwn, gatev, out);
}

// round 4
// speedup vs baseline: 2.1953x; 1.7998x over previous
#include <cuda_runtime.h>
#include <cuda_bf16.h>
#include <math.h>
#include <float.h>
#include <stdint.h>

#define S 2048
#define H 2048
#define NH 16
#define D 128
#define E 8
#define TOPK 4
#define IE 1408
#define IS 5632

// ---------------- scratch (static device globals; no allocation) --------------
__device__ float g_h[S * H];
__device__ float g_q[S * H];
__device__ float g_k[S * H];
__device__ float g_v[S * H];
__device__ float g_scores[(size_t)NH * S * S];
__device__ float g_attn[S * H];
__device__ float g_x1[S * H];
__device__ float g_h2[S * H];
__device__ float g_gb[S * IE];
__device__ float g_ub[S * IE];
__device__ float g_moe[S * H];
__device__ float g_sgb[S * IS];
__device__ float g_sub[S * IS];
__device__ float g_sdwn[S * H];
__device__ float g_wbuf[E * S];
__device__ float g_gatev[S];
__device__ int g_idx[E * S];
__device__ int g_cnt[E];

// ================= tf32 mma.sync GEMM =================
// C[M,N] = A[M,K] @ B[K,N], both row-major fp32, math in tf32 (RNA-rounded).
// CTA tile 128x128, K-tile 16, 8 warps (4x2), warp tile 32x64.
// gatherA: A row = gidx[row]; cntPtr bounds M.
// accMode 0: C[r,c]=v ; accMode 3: C[gidx[r],c] += rowscale[gidx[r]]*v.

__device__ __forceinline__ uint32_t f2tf32(float f) {
    uint32_t r;
    asm("cvt.rna.tf32.f32 %0, %1;" : "=r"(r) : "f"(f));
    return r;
}
__device__ __forceinline__ void mma_tf32(float* d, const uint32_t* a,
                                         const uint32_t* b) {
    asm volatile(
        "mma.sync.aligned.m16n8k8.row.col.f32.tf32.tf32.f32 "
        "{%0,%1,%2,%3}, {%4,%5,%6,%7}, {%8,%9}, {%0,%1,%2,%3};"
        : "+f"(d[0]), "+f"(d[1]), "+f"(d[2]), "+f"(d[3])
        : "r"(a[0]), "r"(a[1]), "r"(a[2]), "r"(a[3]), "r"(b[0]), "r"(b[1]));
}

#define APAD 20  // floats per row (16 data + 4 pad) -> conflict-free frag loads

__global__ __launch_bounds__(256, 2)
void mma_gemm_kernel(const float* __restrict__ A, int lda,
                     const float* __restrict__ B, int ldb,
                     float* __restrict__ C, int ldc,
                     int M, int N, int K,
                     const float* __restrict__ rowscale,
                     const int* __restrict__ gidx,
                     const int* __restrict__ cntPtr,
                     int accMode, int gatherA) {
    __shared__ __align__(16) uint32_t As[2][128 * APAD];
    __shared__ __align__(16) uint32_t Bs[2][128 * APAD];

    const int tid = threadIdx.x;
    const int wid = tid >> 5;
    const int lane = tid & 31;
    const int g = lane >> 2;
    const int t4 = lane & 3;
    const int warpM = wid >> 1;  // 0..3
    const int warpN = wid & 1;   // 0..1

    const int cnt = cntPtr ? *cntPtr : (1 << 30);
    const int mEff = min(M, cnt);
    const int row0 = blockIdx.y * 128;
    const int col0 = blockIdx.x * 128;
    if (row0 >= mEff) return;

    // ---- load plans ----
    // A: 2 float4 tasks: u = tid + 256*j : m = u>>2, c4 = u&3
    const float* aPtr[2];
    int aM[2], aC4[2];
#pragma unroll
    for (int j = 0; j < 2; j++) {
        int u = tid + 256 * j;
        int m = u >> 2, c4 = u & 3;
        aM[j] = m;
        aC4[j] = c4;
        int arow = row0 + m;
        int src;
        if (gatherA) src = (arow < cnt) ? gidx[arow] : 0;
        else src = min(arow, M - 1);
        aPtr[j] = A + (size_t)src * lda + c4 * 4;
    }
    // B: 2 float4 tasks: u = tid + 256*j : k = u&15, n4 = u>>4
    int bK[2], bN4[2];
#pragma unroll
    for (int j = 0; j < 2; j++) {
        int u = tid + 256 * j;
        bK[j] = u & 15;
        bN4[j] = u >> 4;
    }

    float acc[2][8][4];
#pragma unroll
    for (int mt = 0; mt < 2; mt++)
#pragma unroll
        for (int nt = 0; nt < 8; nt++)
#pragma unroll
            for (int r = 0; r < 4; r++) acc[mt][nt][r] = 0.f;

    const int nT = K / 16;
    float4 aReg[2], bReg[2];

    // preload tile 0
#pragma unroll
    for (int j = 0; j < 2; j++) {
        aReg[j] = *reinterpret_cast<const float4*>(aPtr[j]);
        bReg[j] = *reinterpret_cast<const float4*>(
            B + (size_t)bK[j] * ldb + col0 + bN4[j] * 4);
    }
#pragma unroll
    for (int j = 0; j < 2; j++) {
        uint32_t* as = &As[0][aM[j] * APAD + aC4[j] * 4];
        as[0] = f2tf32(aReg[j].x);
        as[1] = f2tf32(aReg[j].y);
        as[2] = f2tf32(aReg[j].z);
        as[3] = f2tf32(aReg[j].w);
        uint32_t* bs = &Bs[0][0];
        int kk = bK[j], nb = bN4[j] * 4;
        bs[(nb + 0) * APAD + kk] = f2tf32(bReg[j].x);
        bs[(nb + 1) * APAD + kk] = f2tf32(bReg[j].y);
        bs[(nb + 2) * APAD + kk] = f2tf32(bReg[j].z);
        bs[(nb + 3) * APAD + kk] = f2tf32(bReg[j].w);
    }
    __syncthreads();

    int buf = 0;
    for (int i = 0; i < nT; i++) {
        const bool more = (i + 1) < nT;
        if (more) {
            int k0 = (i + 1) * 16;
#pragma unroll
            for (int j = 0; j < 2; j++) {
                aReg[j] = *reinterpret_cast<const float4*>(aPtr[j] + k0);
                bReg[j] = *reinterpret_cast<const float4*>(
                    B + (size_t)(k0 + bK[j]) * ldb + col0 + bN4[j] * 4);
            }
        }
        const uint32_t* Asb = As[buf];
        const uint32_t* Bsb = Bs[buf];
#pragma unroll
        for (int kk = 0; kk < 16; kk += 8) {
            uint32_t a[2][4], b[8][2];
#pragma unroll
            for (int mt = 0; mt < 2; mt++) {
                int mrow = warpM * 32 + mt * 16;
                a[mt][0] = Asb[(mrow + g) * APAD + kk + t4];
                a[mt][1] = Asb[(mrow + g + 8) * APAD + kk + t4];
                a[mt][2] = Asb[(mrow + g) * APAD + kk + t4 + 4];
                a[mt][3] = Asb[(mrow + g + 8) * APAD + kk + t4 + 4];
            }
#pragma unroll
            for (int nt = 0; nt < 8; nt++) {
                int ncol = warpN * 64 + nt * 8;
                b[nt][0] = Bsb[(ncol + g) * APAD + kk + t4];
                b[nt][1] = Bsb[(ncol + g) * APAD + kk + t4 + 4];
            }
#pragma unroll
            for (int mt = 0; mt < 2; mt++)
#pragma unroll
                for (int nt = 0; nt < 8; nt++)
                    mma_tf32(acc[mt][nt], a[mt], b[nt]);
        }
        if (more) {
            int nb2 = buf ^ 1;
#pragma unroll
            for (int j = 0; j < 2; j++) {
                uint32_t* as = &As[nb2][aM[j] * APAD + aC4[j] * 4];
                as[0] = f2tf32(aReg[j].x);
                as[1] = f2tf32(aReg[j].y);
                as[2] = f2tf32(aReg[j].z);
                as[3] = f2tf32(aReg[j].w);
                uint32_t* bs = &Bs[nb2][0];
                int kk2 = bK[j], nb = bN4[j] * 4;
                bs[(nb + 0) * APAD + kk2] = f2tf32(bReg[j].x);
                bs[(nb + 1) * APAD + kk2] = f2tf32(bReg[j].y);
                bs[(nb + 2) * APAD + kk2] = f2tf32(bReg[j].z);
                bs[(nb + 3) * APAD + kk2] = f2tf32(bReg[j].w);
            }
        }
        __syncthreads();
        buf ^= 1;
    }

    // ---- epilogue ----
#pragma unroll
    for (int mt = 0; mt < 2; mt++) {
        int rBase = row0 + warpM * 32 + mt * 16 + g;
#pragma unroll
        for (int half = 0; half < 2; half++) {
            int r = rBase + half * 8;
            if (r >= mEff) continue;
            int tgt = r;
            float rs = 1.f;
            if (accMode == 3) {
                tgt = gidx[r];
                rs = rowscale[tgt];
            }
            float* cp = C + (size_t)tgt * ldc + col0 + warpN * 64 + t4 * 2;
#pragma unroll
            for (int nt = 0; nt < 8; nt++) {
                float v0 = acc[mt][nt][half * 2 + 0];
                float v1 = acc[mt][nt][half * 2 + 1];
                float* p = cp + nt * 8;
                if (accMode == 3) {
                    p[0] += rs * v0;
                    p[1] += rs * v1;
                } else {
                    p[0] = v0;
                    p[1] = v1;
                }
            }
        }
    }
}

// ---------------- RMSNorm ----------------
__global__ void rmsnorm_kernel(const float* __restrict__ x,
                               const float* __restrict__ w,
                               float* __restrict__ out) {
    const float* xr = x + (long long)blockIdx.x * H;
    float* orow = out + (long long)blockIdx.x * H;
    __shared__ float red[256];
    float s = 0.f;
    for (int j = threadIdx.x; j < H; j += 256) {
        float v = xr[j];
        s += v * v;
    }
    red[threadIdx.x] = s;
    __syncthreads();
    for (int st = 128; st > 0; st >>= 1) {
        if (threadIdx.x < st) red[threadIdx.x] += red[threadIdx.x + st];
        __syncthreads();
    }
    float inv = 1.0f / sqrtf(red[0] / (float)H + 1e-6f);
    for (int j = threadIdx.x; j < H; j += 256) orow[j] = w[j] * xr[j] * inv;
}

// ---------------- fp32 SGEMM (upstream of router) ----------------
__global__ __launch_bounds__(256, 2)
void sgemm_kernel(const float* __restrict__ A, int lda, long long sA,
                  const float* __restrict__ B, int ldb, long long sB,
                  float* __restrict__ C, int ldc, long long sC,
                  int K,
                  const float* __restrict__ bias,
                  const float* __restrict__ residual, int ldr,
                  int transB, int causal, int kLimit,
                  float scale) {
    __shared__ __align__(16) float As[2][8][128];
    __shared__ __align__(16) float Bs[2][8][128];

    const int bz = blockIdx.z;
    A += (long long)bz * sA;
    B += (long long)bz * sB;
    C += (long long)bz * sC;

    const int row0 = blockIdx.y * 128;
    const int col0 = blockIdx.x * 128;
    if (causal && col0 > row0) return;
    int Keff = kLimit ? min(K, row0 + 128) : K;

    const int tid = threadIdx.x;
    const int trow = (tid >> 4) * 8;
    const int tcol = (tid & 15) * 8;

    const int aRow = tid >> 1;
    const int aCol = (tid & 1) * 4;
    const int bRow = tid >> 5;
    const int bCol = (tid & 31) * 4;

    const float* Aptr = A + (long long)(row0 + aRow) * lda + aCol;
    const float* BptrNN = B + (long long)bRow * ldb + col0 + bCol;
    const float* BptrNT = B + (long long)(col0 + aRow) * ldb + aCol;

    unsigned long long acc[4][8];
#pragma unroll
    for (int i = 0; i < 4; i++)
#pragma unroll
        for (int j = 0; j < 8; j++) acc[i][j] = 0ull;

    float4 av = *reinterpret_cast<const float4*>(Aptr);
    float4 bv = transB ? *reinterpret_cast<const float4*>(BptrNT)
                       : *reinterpret_cast<const float4*>(BptrNN);
    As[0][aCol + 0][aRow] = av.x;
    As[0][aCol + 1][aRow] = av.y;
    As[0][aCol + 2][aRow] = av.z;
    As[0][aCol + 3][aRow] = av.w;
    if (transB) {
        Bs[0][aCol + 0][aRow] = bv.x;
        Bs[0][aCol + 1][aRow] = bv.y;
        Bs[0][aCol + 2][aRow] = bv.z;
        Bs[0][aCol + 3][aRow] = bv.w;
    } else {
        *reinterpret_cast<float4*>(&Bs[0][bRow][bCol]) = bv;
    }
    __syncthreads();

    int buf = 0;
    for (int k0 = 0; k0 < Keff; k0 += 8) {
        const bool more = (k0 + 8) < Keff;
        if (more) {
            av = *reinterpret_cast<const float4*>(Aptr + k0 + 8);
            bv = transB
                     ? *reinterpret_cast<const float4*>(BptrNT + k0 + 8)
                     : *reinterpret_cast<const float4*>(BptrNN + (long long)(k0 + 8) * ldb);
        }
#pragma unroll
        for (int kk = 0; kk < 8; kk++) {
            ulonglong2 a01 = *reinterpret_cast<const ulonglong2*>(&As[buf][kk][trow]);
            ulonglong2 a23 = *reinterpret_cast<const ulonglong2*>(&As[buf][kk][trow + 4]);
            float4 b0 = *reinterpret_cast<const float4*>(&Bs[buf][kk][tcol]);
            float4 b1 = *reinterpret_cast<const float4*>(&Bs[buf][kk][tcol + 4]);
            unsigned long long ap[4];
            ap[0] = a01.x; ap[1] = a01.y; ap[2] = a23.x; ap[3] = a23.y;
            float bvals[8];
            bvals[0] = b0.x; bvals[1] = b0.y; bvals[2] = b0.z; bvals[3] = b0.w;
            bvals[4] = b1.x; bvals[5] = b1.y; bvals[6] = b1.z; bvals[7] = b1.w;
#pragma unroll
            for (int j = 0; j < 8; j++) {
                unsigned long long bp;
                asm("mov.b64 %0, {%1, %1};" : "=l"(bp) : "f"(bvals[j]));
#pragma unroll
                for (int i2 = 0; i2 < 4; i2++) {
                    asm("fma.rn.f32x2 %0, %1, %2, %0;"
                        : "+l"(acc[i2][j]) : "l"(ap[i2]), "l"(bp));
                }
            }
        }
        if (more) {
            int nb = buf ^ 1;
            As[nb][aCol + 0][aRow] = av.x;
            As[nb][aCol + 1][aRow] = av.y;
            As[nb][aCol + 2][aRow] = av.z;
            As[nb][aCol + 3][aRow] = av.w;
            if (transB) {
                Bs[nb][aCol + 0][aRow] = bv.x;
                Bs[nb][aCol + 1][aRow] = bv.y;
                Bs[nb][aCol + 2][aRow] = bv.z;
                Bs[nb][aCol + 3][aRow] = bv.w;
            } else {
                *reinterpret_cast<float4*>(&Bs[nb][bRow][bCol]) = bv;
            }
        }
        __syncthreads();
        buf ^= 1;
    }

#pragma unroll
    for (int i2 = 0; i2 < 4; i2++) {
#pragma unroll
        for (int j = 0; j < 8; j++) {
            float lo, hi;
            asm("mov.b64 {%0, %1}, %2;" : "=f"(lo), "=f"(hi) : "l"(acc[i2][j]));
            int c = col0 + tcol + j;
#pragma unroll
            for (int half = 0; half < 2; half++) {
                int r = row0 + trow + 2 * i2 + half;
                float v = (half == 0 ? lo : hi) * scale;
                if (bias) v += bias[c];
                if (residual) v += residual[(long long)r * ldr + c];
                C[(long long)r * ldc + c] = v;
            }
        }
    }
}

// ---------------- RoPE ----------------
__global__ void rope_kernel(float* __restrict__ q, float* __restrict__ k) {
    int s = blockIdx.x;
    int h = blockIdx.y;
    int j = threadIdx.x;
    double invd = pow(1.0e6, -(double)j / 64.0);
    float ang = (float)((double)s * invd);
    float c = cosf(ang), sn = sinf(ang);
    long long base = ((long long)s * NH + h) * D;
    float q1 = q[base + j], q2 = q[base + j + 64];
    q[base + j] = q1 * c - q2 * sn;
    q[base + j + 64] = q2 * c + q1 * sn;
    float k1 = k[base + j], k2 = k[base + j + 64];
    k[base + j] = k1 * c - k2 * sn;
    k[base + j + 64] = k2 * c + k1 * sn;
}

// ---------------- causal row softmax ----------------
__global__ void softmax_kernel(float* __restrict__ scores) {
    int r = blockIdx.x;
    float* row = scores + ((long long)blockIdx.y * S + r) * S;
    const int limit = r + 1;
    const int rBlk = ((r >> 7) + 1) << 7;
    __shared__ float red[256];
    int tid = threadIdx.x;
    float m = -FLT_MAX;
    for (int j = tid; j < limit; j += 256) m = fmaxf(m, row[j]);
    red[tid] = m;
    __syncthreads();
    for (int st = 128; st > 0; st >>= 1) {
        if (tid < st) red[tid] = fmaxf(red[tid], red[tid + st]);
        __syncthreads();
    }
    m = red[0];
    __syncthreads();
    float sum = 0.f;
    for (int j = tid; j < limit; j += 256) {
        float e = expf(row[j] - m);
        row[j] = e;
        sum += e;
    }
    red[tid] = sum;
    __syncthreads();
    for (int st = 128; st > 0; st >>= 1) {
        if (tid < st) red[tid] += red[tid + st];
        __syncthreads();
    }
    float inv = 1.0f / red[0];
    for (int j = tid; j < limit; j += 256) row[j] *= inv;
    for (int j = limit + tid; j < rBlk; j += 256) row[j] = 0.f;
}

// ---------------- router ----------------
__global__ void router_kernel(const float* __restrict__ h2,
                              const float* __restrict__ gate_w,
                              float* __restrict__ logits_out,
                              float* __restrict__ wbuf,
                              int* __restrict__ idxbuf,
                              int* __restrict__ cnt) {
    int s = blockIdx.x;
    const float* hr = h2 + (long long)s * H;
    __shared__ float red[256][E];
    float p[E];
#pragma unroll
    for (int e = 0; e < E; e++) p[e] = 0.f;
    for (int j = threadIdx.x; j < H; j += 256) {
        float hv = hr[j];
#pragma unroll
        for (int e = 0; e < E; e++) p[e] += hv * gate_w[j * E + e];
    }
#pragma unroll
    for (int e = 0; e < E; e++) red[threadIdx.x][e] = p[e];
    __syncthreads();
    for (int st = 128; st > 0; st >>= 1) {
        if (threadIdx.x < st)
#pragma unroll
            for (int e = 0; e < E; e++) red[threadIdx.x][e] += red[threadIdx.x + st][e];
        __syncthreads();
    }
    if (threadIdx.x == 0) {
        float logit[E];
        float m = -FLT_MAX;
#pragma unroll
        for (int e = 0; e < E; e++) {
            logit[e] = red[0][e];
            logits_out[(long long)s * E + e] = logit[e];
            m = fmaxf(m, logit[e]);
        }
        float sum = 0.f, rw[E];
#pragma unroll
        for (int e = 0; e < E; e++) {
            rw[e] = expf(logit[e] - m);
            sum += rw[e];
        }
        float inv = 1.0f / sum;
#pragma unroll
        for (int e = 0; e < E; e++) rw[e] *= inv;
        float wsel[E];
        bool used[E];
#pragma unroll
        for (int e = 0; e < E; e++) { wsel[e] = 0.f; used[e] = false; }
        for (int k = 0; k < TOPK; k++) {
            int best = -1;
            float bv = -FLT_MAX;
            for (int e = 0; e < E; e++)
                if (!used[e] && rw[e] > bv) { bv = rw[e]; best = e; }
            used[best] = true;
            wsel[best] = bv;
        }
#pragma unroll
        for (int e = 0; e < E; e++) {
            wbuf[e * S + s] = wsel[e];
            if (wsel[e] > 0.f) {
                int pos = atomicAdd(&cnt[e], 1);
                idxbuf[e * S + pos] = s;
            }
        }
    }
}

// ---------------- h2 . sgate ----------------
__global__ void rowdot_kernel(const float* __restrict__ h2,
                              const float* __restrict__ sgate,
                              float* __restrict__ gatev) {
    int s = blockIdx.x;
    const float* hr = h2 + (long long)s * H;
    __shared__ float red[256];
    float acc = 0.f;
    for (int j = threadIdx.x; j < H; j += 256) acc += hr[j] * sgate[j];
    red[threadIdx.x] = acc;
    __syncthreads();
    for (int st = 128; st > 0; st >>= 1) {
        if (threadIdx.x < st) red[threadIdx.x] += red[threadIdx.x + st];
        __syncthreads();
    }
    if (threadIdx.x == 0) gatev[s] = red[0];
}

// ---------------- silu(g)*u (count-bounded) ----------------
__global__ void silu_mul_kernel(float* __restrict__ g, const float* __restrict__ u,
                                long long n, const int* __restrict__ cntPtr,
                                int rowWidth) {
    long long i = (long long)blockIdx.x * 256 + threadIdx.x;
    if (cntPtr) {
        long long lim = (long long)(*cntPtr) * rowWidth;
        if (i >= lim) return;
    }
    if (i < n) {
        float x = g[i];
        float sg = 1.0f / (1.0f + expf(-x));
        g[i] = x * sg * u[i];
    }
}

// ---------------- final combine ----------------
__global__ void final_kernel(const float* __restrict__ x1,
                             const float* __restrict__ moe,
                             const float* __restrict__ sdwn,
                             const float* __restrict__ gatev,
                             float* __restrict__ out) {
    long long i = (long long)blockIdx.x * 256 + threadIdx.x;
    int srow = (int)(i / H);
    float gv = 1.0f / (1.0f + expf(-gatev[srow]));
    out[i] = x1[i] + moe[i] + gv * sdwn[i];
}

// ---------------- host ----------------
static void launch_sgemm(const float* A, int lda, long long sA,
                         const float* B, int ldb, long long sB,
                         float* C, int ldc, long long sC,
                         int M, int N, int K, int batch,
                         const float* bias, const float* res, int ldr,
                         int transB, int causal, int kLimit, float scale) {
    dim3 grid(N / 128, M / 128, batch);
    sgemm_kernel<<<grid, 256>>>(A, lda, sA, B, ldb, sB, C, ldc, sC, K,
                                bias, res, ldr, transB, causal, kLimit, scale);
}

static void launch_mma(const float* A, int lda, const float* B, int ldb,
                       float* C, int ldc, int M, int N, int K,
                       const float* rowscale, const int* gidx, const int* cnt,
                       int accMode, int gatherA) {
    dim3 grid(N / 128, (M + 127) / 128);
    mma_gemm_kernel<<<grid, 256>>>(A, lda, B, ldb, C, ldc, M, N, K,
                                   rowscale, gidx, cnt, accMode, gatherA);
}

extern "C" void kernel_launch(void* const* d_in, const int* in_sizes, int n_in,
                              void* d_out, int out_size) {
    (void)in_sizes; (void)n_in; (void)out_size;
    const float* x     = (const float*)d_in[0];
    const float* ln1   = (const float*)d_in[1];
    const float* ln2   = (const float*)d_in[2];
    const float* wq    = (const float*)d_in[3];
    const float* bq    = (const float*)d_in[4];
    const float* wk    = (const float*)d_in[5];
    const float* bk    = (const float*)d_in[6];
    const float* wv    = (const float*)d_in[7];
    const float* bv    = (const float*)d_in[8];
    const float* wo    = (const float*)d_in[9];
    const float* gatew = (const float*)d_in[10];
    const float* eg    = (const float*)d_in[11];
    const float* eu    = (const float*)d_in[12];
    const float* ed    = (const float*)d_in[13];
    const float* sg    = (const float*)d_in[14];
    const float* su    = (const float*)d_in[15];
    const float* sd    = (const float*)d_in[16];
    const float* sgate = (const float*)d_in[17];
    float* out = (float*)d_out;

    float *h, *q, *k, *v, *scores, *attn, *x1, *h2, *gb, *ub, *moe, *sgb, *sub,
        *sdwn, *wbuf, *gatev;
    int *idx, *cnt;
    cudaGetSymbolAddress((void**)&h, g_h);
    cudaGetSymbolAddress((void**)&q, g_q);
    cudaGetSymbolAddress((void**)&k, g_k);
    cudaGetSymbolAddress((void**)&v, g_v);
    cudaGetSymbolAddress((void**)&scores, g_scores);
    cudaGetSymbolAddress((void**)&attn, g_attn);
    cudaGetSymbolAddress((void**)&x1, g_x1);
    cudaGetSymbolAddress((void**)&h2, g_h2);
    cudaGetSymbolAddress((void**)&gb, g_gb);
    cudaGetSymbolAddress((void**)&ub, g_ub);
    cudaGetSymbolAddress((void**)&moe, g_moe);
    cudaGetSymbolAddress((void**)&sgb, g_sgb);
    cudaGetSymbolAddress((void**)&sub, g_sub);
    cudaGetSymbolAddress((void**)&sdwn, g_sdwn);
    cudaGetSymbolAddress((void**)&wbuf, g_wbuf);
    cudaGetSymbolAddress((void**)&gatev, g_gatev);
    cudaGetSymbolAddress((void**)&idx, g_idx);
    cudaGetSymbolAddress((void**)&cnt, g_cnt);

    const float ascale = 0.08838834764831845f;

    // 1. h = rmsnorm(x, ln1)
    rmsnorm_kernel<<<S, 256>>>(x, ln1, h);

    // 2. q,k,v = h@W + b  (fp32 upstream of router)
    launch_sgemm(h, H, 0, wq, NH * D, 0, q, NH * D, 0, S, NH * D, H, 1, bq,
                 nullptr, 0, 0, 0, 0, 1.0f);
    launch_sgemm(h, H, 0, wk, NH * D, 0, k, NH * D, 0, S, NH * D, H, 1, bk,
                 nullptr, 0, 0, 0, 0, 1.0f);
    launch_sgemm(h, H, 0, wv, NH * D, 0, v, NH * D, 0, S, NH * D, H, 1, bv,
                 nullptr, 0, 0, 0, 0, 1.0f);

    // 3. RoPE
    rope_kernel<<<dim3(S, NH), 64>>>(q, k);

    // 4. scores (lower blocks only)
    launch_sgemm(q, NH * D, D, k, NH * D, D, scores, S, (long long)S * S,
                 S, S, D, NH, nullptr, nullptr, 0, 1, 1, 0, ascale);

    // 5. causal softmax
    softmax_kernel<<<dim3(S, NH), 256>>>(scores);

    // 6. attn = probs @ v
    launch_sgemm(scores, S, (long long)S * S, v, NH * D, D, attn, NH * D, D,
                 S, D, S, NH, nullptr, nullptr, 0, 0, 0, 1, 1.0f);

    // 7. x1 = x + attn @ wo
    launch_sgemm(attn, NH * D, 0, wo, H, 0, x1, H, 0, S, H, NH * D, 1, nullptr,
                 x, H, 0, 0, 0, 1.0f);

    // 8. h2 = rmsnorm(x1, ln2)
    rmsnorm_kernel<<<S, 256>>>(x1, ln2, h2);

    // 9. router
    cudaMemsetAsync(cnt, 0, E * sizeof(int));
    router_kernel<<<S, 256>>>(h2, gatew, out + (long long)S * H, wbuf, idx, cnt);

    // 10. sparse MoE on tf32 mma
    cudaMemsetAsync(moe, 0, (size_t)S * H * sizeof(float));
    for (int e = 0; e < E; e++) {
        const float* ege = eg + (long long)e * H * IE;
        const float* eue = eu + (long long)e * H * IE;
        const float* ede = ed + (long long)e * IE * H;
        launch_mma(h2, H, ege, IE, gb, IE, S, IE, H, nullptr, idx + e * S,
                   cnt + e, 0, 1);
        launch_mma(h2, H, eue, IE, ub, IE, S, IE, H, nullptr, idx + e * S,
                   cnt + e, 0, 1);
        long long n = (long long)S * IE;
        silu_mul_kernel<<<(unsigned)((n + 255) / 256), 256>>>(gb, ub, n,
                                                              cnt + e, IE);
        launch_mma(gb, IE, ede, H, moe, H, S, H, IE, wbuf + e * S, idx + e * S,
                   cnt + e, 3, 0);
    }

    // 11. shared expert on tf32 mma
    launch_mma(h2, H, sg, IS, sgb, IS, S, IS, H, nullptr, nullptr, nullptr, 0, 0);
    launch_mma(h2, H, su, IS, sub, IS, S, IS, H, nullptr, nullptr, nullptr, 0, 0);
    {
        long long n = (long long)S * IS;
        silu_mul_kernel<<<(unsigned)((n + 255) / 256), 256>>>(sgb, sub, n,
                                                              nullptr, 0);
    }
    launch_mma(sgb, IS, sd, H, sdwn, H, S, H, IS, nullptr, nullptr, nullptr, 0, 0);

    // 12. gate scalar
    rowdot_kernel<<<S, 256>>>(h2, sgate, gatev);

    // 13. combine
    final_kernel<<<(S * H) / 256, 256>>>(x1, moe, sdwn, gatev, out);
}

// round 5
// speedup vs baseline: 2.6471x; 1.2058x over previous
#include <cuda_runtime.h>
#include <cuda_bf16.h>
#include <math.h>
#include <float.h>
#include <stdint.h>

#define S 2048
#define H 2048
#define NH 16
#define D 128
#define E 8
#define TOPK 4
#define IE 1408
#define IS 5632

// ---------------- scratch (static device globals; no allocation) --------------
__device__ float g_h[S * H];
__device__ float g_q[S * H];
__device__ float g_k[S * H];
__device__ float g_v[S * H];
__device__ float g_scores[(size_t)NH * S * S];
__device__ float g_attn[S * H];
__device__ float g_x1[S * H];
__device__ float g_h2[S * H];
__device__ float g_gb[(size_t)E * S * IE];
__device__ float g_ub[(size_t)E * S * IE];
__device__ float g_eo[(size_t)E * S * H];
__device__ float g_sgb[S * IS];
__device__ float g_sub[S * IS];
__device__ float g_sdwn[S * H];
__device__ float g_gatev[S];
__device__ int g_idx[E * S];
__device__ int g_cnt[E];
__device__ int g_tokmap[S * TOPK];
__device__ float g_tokw[S * TOPK];

// ================= tf32 mma.sync GEMM =================
// CTA tile 128x128, K-tile 16, 8 warps (4x2), warp tile 32x64.
// z-batched: e = z >> eShift; which = z & ((1<<eShift)-1).
// A += e*aStrE ; B = (which ? B1 : B0) + e*bStrE ; C = (which ? C1 : C0) + e*cStrE.
// gidxBase: per-e gather list for A rows; cntBase: per-e row count.

__device__ __forceinline__ uint32_t f2tf32(float f) {
    uint32_t r;
    asm("cvt.rna.tf32.f32 %0, %1;" : "=r"(r) : "f"(f));
    return r;
}
__device__ __forceinline__ void mma_tf32(float* d, const uint32_t* a,
                                         const uint32_t* b) {
    asm volatile(
        "mma.sync.aligned.m16n8k8.row.col.f32.tf32.tf32.f32 "
        "{%0,%1,%2,%3}, {%4,%5,%6,%7}, {%8,%9}, {%0,%1,%2,%3};"
        : "+f"(d[0]), "+f"(d[1]), "+f"(d[2]), "+f"(d[3])
        : "r"(a[0]), "r"(a[1]), "r"(a[2]), "r"(a[3]), "r"(b[0]), "r"(b[1]));
}

#define APAD 20

__global__ __launch_bounds__(256, 2)
void mma_gemm_kernel(const float* __restrict__ A, int lda, long long aStrE,
                     const float* __restrict__ B0, const float* __restrict__ B1,
                     int ldb, long long bStrE,
                     float* __restrict__ C0, float* __restrict__ C1,
                     int ldc, long long cStrE,
                     int M, int N, int K,
                     const int* __restrict__ gidxBase, int gidxStr,
                     const int* __restrict__ cntBase, int eShift) {
    __shared__ __align__(16) uint32_t As[2][128 * APAD];
    __shared__ __align__(16) uint32_t Bs[2][128 * APAD];

    const int z = blockIdx.z;
    const int e = z >> eShift;
    const int which = z & ((1 << eShift) - 1);
    const float* B = (which ? B1 : B0) + (long long)e * bStrE;
    float* C = (which ? C1 : C0) + (long long)e * cStrE;
    A += (long long)e * aStrE;

    const int cnt = cntBase ? cntBase[e] : M;
    const int mEff = min(M, cnt);
    const int row0 = blockIdx.y * 128;
    const int col0 = blockIdx.x * 128;
    if (row0 >= mEff) return;
    const int* gidx = gidxBase ? gidxBase + (long long)e * gidxStr : nullptr;

    const int tid = threadIdx.x;
    const int wid = tid >> 5;
    const int lane = tid & 31;
    const int g = lane >> 2;
    const int t4 = lane & 3;
    const int warpM = wid >> 1;
    const int warpN = wid & 1;

    // ---- load plans ----
    const float* aPtr[2];
    int aM[2], aC4[2];
#pragma unroll
    for (int j = 0; j < 2; j++) {
        int u = tid + 256 * j;
        int m = u >> 2, c4 = u & 3;
        aM[j] = m;
        aC4[j] = c4;
        int arow = row0 + m;
        int src;
        if (gidx) src = (arow < cnt) ? gidx[arow] : 0;
        else src = min(arow, M - 1);
        aPtr[j] = A + (size_t)src * lda + c4 * 4;
    }
    int bK[2], bN4[2];
#pragma unroll
    for (int j = 0; j < 2; j++) {
        int u = tid + 256 * j;
        bK[j] = u & 15;
        bN4[j] = u >> 4;
    }

    float acc[2][8][4];
#pragma unroll
    for (int mt = 0; mt < 2; mt++)
#pragma unroll
        for (int nt = 0; nt < 8; nt++)
#pragma unroll
            for (int r = 0; r < 4; r++) acc[mt][nt][r] = 0.f;

    const int nT = K / 16;
    float4 aReg[2], bReg[2];

#pragma unroll
    for (int j = 0; j < 2; j++) {
        aReg[j] = *reinterpret_cast<const float4*>(aPtr[j]);
        bReg[j] = *reinterpret_cast<const float4*>(
            B + (size_t)bK[j] * ldb + col0 + bN4[j] * 4);
    }
#pragma unroll
    for (int j = 0; j < 2; j++) {
        uint32_t* as = &As[0][aM[j] * APAD + aC4[j] * 4];
        as[0] = f2tf32(aReg[j].x);
        as[1] = f2tf32(aReg[j].y);
        as[2] = f2tf32(aReg[j].z);
        as[3] = f2tf32(aReg[j].w);
        uint32_t* bs = &Bs[0][0];
        int kk = bK[j], nb = bN4[j] * 4;
        bs[(nb + 0) * APAD + kk] = f2tf32(bReg[j].x);
        bs[(nb + 1) * APAD + kk] = f2tf32(bReg[j].y);
        bs[(nb + 2) * APAD + kk] = f2tf32(bReg[j].z);
        bs[(nb + 3) * APAD + kk] = f2tf32(bReg[j].w);
    }
    __syncthreads();

    int buf = 0;
    for (int i = 0; i < nT; i++) {
        const bool more = (i + 1) < nT;
        if (more) {
            int k0 = (i + 1) * 16;
#pragma unroll
            for (int j = 0; j < 2; j++) {
                aReg[j] = *reinterpret_cast<const float4*>(aPtr[j] + k0);
                bReg[j] = *reinterpret_cast<const float4*>(
                    B + (size_t)(k0 + bK[j]) * ldb + col0 + bN4[j] * 4);
            }
        }
        const uint32_t* Asb = As[buf];
        const uint32_t* Bsb = Bs[buf];
#pragma unroll
        for (int kk = 0; kk < 16; kk += 8) {
            uint32_t a[2][4], b[8][2];
#pragma unroll
            for (int mt = 0; mt < 2; mt++) {
                int mrow = warpM * 32 + mt * 16;
                a[mt][0] = Asb[(mrow + g) * APAD + kk + t4];
                a[mt][1] = Asb[(mrow + g + 8) * APAD + kk + t4];
                a[mt][2] = Asb[(mrow + g) * APAD + kk + t4 + 4];
                a[mt][3] = Asb[(mrow + g + 8) * APAD + kk + t4 + 4];
            }
#pragma unroll
            for (int nt = 0; nt < 8; nt++) {
                int ncol = warpN * 64 + nt * 8;
                b[nt][0] = Bsb[(ncol + g) * APAD + kk + t4];
                b[nt][1] = Bsb[(ncol + g) * APAD + kk + t4 + 4];
            }
#pragma unroll
            for (int mt = 0; mt < 2; mt++)
#pragma unroll
                for (int nt = 0; nt < 8; nt++)
                    mma_tf32(acc[mt][nt], a[mt], b[nt]);
        }
        if (more) {
            int nb2 = buf ^ 1;
#pragma unroll
            for (int j = 0; j < 2; j++) {
                uint32_t* as = &As[nb2][aM[j] * APAD + aC4[j] * 4];
                as[0] = f2tf32(aReg[j].x);
                as[1] = f2tf32(aReg[j].y);
                as[2] = f2tf32(aReg[j].z);
                as[3] = f2tf32(aReg[j].w);
                uint32_t* bs = &Bs[nb2][0];
                int kk2 = bK[j], nb = bN4[j] * 4;
                bs[(nb + 0) * APAD + kk2] = f2tf32(bReg[j].x);
                bs[(nb + 1) * APAD + kk2] = f2tf32(bReg[j].y);
                bs[(nb + 2) * APAD + kk2] = f2tf32(bReg[j].z);
                bs[(nb + 3) * APAD + kk2] = f2tf32(bReg[j].w);
            }
        }
        __syncthreads();
        buf ^= 1;
    }

#pragma unroll
    for (int mt = 0; mt < 2; mt++) {
        int rBase = row0 + warpM * 32 + mt * 16 + g;
#pragma unroll
        for (int half = 0; half < 2; half++) {
            int r = rBase + half * 8;
            if (r >= mEff) continue;
            float* cp = C + (size_t)r * ldc + col0 + warpN * 64 + t4 * 2;
#pragma unroll
            for (int nt = 0; nt < 8; nt++) {
                cp[nt * 8 + 0] = acc[mt][nt][half * 2 + 0];
                cp[nt * 8 + 1] = acc[mt][nt][half * 2 + 1];
            }
        }
    }
}

// ---------------- RMSNorm ----------------
__global__ void rmsnorm_kernel(const float* __restrict__ x,
                               const float* __restrict__ w,
                               float* __restrict__ out) {
    const float* xr = x + (long long)blockIdx.x * H;
    float* orow = out + (long long)blockIdx.x * H;
    __shared__ float red[256];
    float s = 0.f;
    for (int j = threadIdx.x; j < H; j += 256) {
        float v = xr[j];
        s += v * v;
    }
    red[threadIdx.x] = s;
    __syncthreads();
    for (int st = 128; st > 0; st >>= 1) {
        if (threadIdx.x < st) red[threadIdx.x] += red[threadIdx.x + st];
        __syncthreads();
    }
    float inv = 1.0f / sqrtf(red[0] / (float)H + 1e-6f);
    for (int j = threadIdx.x; j < H; j += 256) orow[j] = w[j] * xr[j] * inv;
}

// ---------------- fp32 SGEMM (upstream of router) ----------------
// selMode: z selects among (B,bias,C)/(B1,bias1,C1)/(B2,bias2,C2); else z-strides.
__global__ __launch_bounds__(256, 2)
void sgemm_kernel(const float* __restrict__ A, int lda, long long sA,
                  const float* __restrict__ B, int ldb, long long sB,
                  float* __restrict__ C, int ldc, long long sC,
                  int K,
                  const float* __restrict__ bias,
                  const float* __restrict__ residual, int ldr,
                  int transB, int causal, int kLimit, float scale,
                  int selMode,
                  const float* B1, const float* B2,
                  const float* bias1, const float* bias2,
                  float* C1, float* C2) {
    __shared__ __align__(16) float As[2][8][128];
    __shared__ __align__(16) float Bs[2][8][128];

    const int bz = blockIdx.z;
    if (selMode) {
        if (bz == 1) { B = B1; bias = bias1; C = C1; }
        else if (bz == 2) { B = B2; bias = bias2; C = C2; }
    } else {
        A += (long long)bz * sA;
        B += (long long)bz * sB;
        C += (long long)bz * sC;
    }

    const int row0 = blockIdx.y * 128;
    const int col0 = blockIdx.x * 128;
    if (causal && col0 > row0) return;
    int Keff = kLimit ? min(K, row0 + 128) : K;

    const int tid = threadIdx.x;
    const int trow = (tid >> 4) * 8;
    const int tcol = (tid & 15) * 8;

    const int aRow = tid >> 1;
    const int aCol = (tid & 1) * 4;
    const int bRow = tid >> 5;
    const int bCol = (tid & 31) * 4;

    const float* Aptr = A + (long long)(row0 + aRow) * lda + aCol;
    const float* BptrNN = B + (long long)bRow * ldb + col0 + bCol;
    const float* BptrNT = B + (long long)(col0 + aRow) * ldb + aCol;

    unsigned long long acc[4][8];
#pragma unroll
    for (int i = 0; i < 4; i++)
#pragma unroll
        for (int j = 0; j < 8; j++) acc[i][j] = 0ull;

    float4 av = *reinterpret_cast<const float4*>(Aptr);
    float4 bv = transB ? *reinterpret_cast<const float4*>(BptrNT)
                       : *reinterpret_cast<const float4*>(BptrNN);
    As[0][aCol + 0][aRow] = av.x;
    As[0][aCol + 1][aRow] = av.y;
    As[0][aCol + 2][aRow] = av.z;
    As[0][aCol + 3][aRow] = av.w;
    if (transB) {
        Bs[0][aCol + 0][aRow] = bv.x;
        Bs[0][aCol + 1][aRow] = bv.y;
        Bs[0][aCol + 2][aRow] = bv.z;
        Bs[0][aCol + 3][aRow] = bv.w;
    } else {
        *reinterpret_cast<float4*>(&Bs[0][bRow][bCol]) = bv;
    }
    __syncthreads();

    int buf = 0;
    for (int k0 = 0; k0 < Keff; k0 += 8) {
        const bool more = (k0 + 8) < Keff;
        if (more) {
            av = *reinterpret_cast<const float4*>(Aptr + k0 + 8);
            bv = transB
                     ? *reinterpret_cast<const float4*>(BptrNT + k0 + 8)
                     : *reinterpret_cast<const float4*>(BptrNN + (long long)(k0 + 8) * ldb);
        }
#pragma unroll
        for (int kk = 0; kk < 8; kk++) {
            ulonglong2 a01 = *reinterpret_cast<const ulonglong2*>(&As[buf][kk][trow]);
            ulonglong2 a23 = *reinterpret_cast<const ulonglong2*>(&As[buf][kk][trow + 4]);
            float4 b0 = *reinterpret_cast<const float4*>(&Bs[buf][kk][tcol]);
            float4 b1 = *reinterpret_cast<const float4*>(&Bs[buf][kk][tcol + 4]);
            unsigned long long ap[4];
            ap[0] = a01.x; ap[1] = a01.y; ap[2] = a23.x; ap[3] = a23.y;
            float bvals[8];
            bvals[0] = b0.x; bvals[1] = b0.y; bvals[2] = b0.z; bvals[3] = b0.w;
            bvals[4] = b1.x; bvals[5] = b1.y; bvals[6] = b1.z; bvals[7] = b1.w;
#pragma unroll
            for (int j = 0; j < 8; j++) {
                unsigned long long bp;
                asm("mov.b64 %0, {%1, %1};" : "=l"(bp) : "f"(bvals[j]));
#pragma unroll
                for (int i2 = 0; i2 < 4; i2++) {
                    asm("fma.rn.f32x2 %0, %1, %2, %0;"
                        : "+l"(acc[i2][j]) : "l"(ap[i2]), "l"(bp));
                }
            }
        }
        if (more) {
            int nb = buf ^ 1;
            As[nb][aCol + 0][aRow] = av.x;
            As[nb][aCol + 1][aRow] = av.y;
            As[nb][aCol + 2][aRow] = av.z;
            As[nb][aCol + 3][aRow] = av.w;
            if (transB) {
                Bs[nb][aCol + 0][aRow] = bv.x;
                Bs[nb][aCol + 1][aRow] = bv.y;
                Bs[nb][aCol + 2][aRow] = bv.z;
                Bs[nb][aCol + 3][aRow] = bv.w;
            } else {
                *reinterpret_cast<float4*>(&Bs[nb][bRow][bCol]) = bv;
            }
        }
        __syncthreads();
        buf ^= 1;
    }

#pragma unroll
    for (int i2 = 0; i2 < 4; i2++) {
#pragma unroll
        for (int j = 0; j < 8; j++) {
            float lo, hi;
            asm("mov.b64 {%0, %1}, %2;" : "=f"(lo), "=f"(hi) : "l"(acc[i2][j]));
            int c = col0 + tcol + j;
#pragma unroll
            for (int half = 0; half < 2; half++) {
                int r = row0 + trow + 2 * i2 + half;
                float v = (half == 0 ? lo : hi) * scale;
                if (bias) v += bias[c];
                if (residual) v += residual[(long long)r * ldr + c];
                C[(long long)r * ldc + c] = v;
            }
        }
    }
}

// ---------------- RoPE ----------------
__global__ void rope_kernel(float* __restrict__ q, float* __restrict__ k) {
    int s = blockIdx.x;
    int h = blockIdx.y;
    int j = threadIdx.x;
    double invd = pow(1.0e6, -(double)j / 64.0);
    float ang = (float)((double)s * invd);
    float c = cosf(ang), sn = sinf(ang);
    long long base = ((long long)s * NH + h) * D;
    float q1 = q[base + j], q2 = q[base + j + 64];
    q[base + j] = q1 * c - q2 * sn;
    q[base + j + 64] = q2 * c + q1 * sn;
    float k1 = k[base + j], k2 = k[base + j + 64];
    k[base + j] = k1 * c - k2 * sn;
    k[base + j + 64] = k2 * c + k1 * sn;
}

// ---------------- causal row softmax ----------------
__global__ void softmax_kernel(float* __restrict__ scores) {
    int r = blockIdx.x;
    float* row = scores + ((long long)blockIdx.y * S + r) * S;
    const int limit = r + 1;
    const int rBlk = ((r >> 7) + 1) << 7;
    __shared__ float red[256];
    int tid = threadIdx.x;
    float m = -FLT_MAX;
    for (int j = tid; j < limit; j += 256) m = fmaxf(m, row[j]);
    red[tid] = m;
    __syncthreads();
    for (int st = 128; st > 0; st >>= 1) {
        if (tid < st) red[tid] = fmaxf(red[tid], red[tid + st]);
        __syncthreads();
    }
    m = red[0];
    __syncthreads();
    float sum = 0.f;
    for (int j = tid; j < limit; j += 256) {
        float e = expf(row[j] - m);
        row[j] = e;
        sum += e;
    }
    red[tid] = sum;
    __syncthreads();
    for (int st = 128; st > 0; st >>= 1) {
        if (tid < st) red[tid] += red[tid + st];
        __syncthreads();
    }
    float inv = 1.0f / red[0];
    for (int j = tid; j < limit; j += 256) row[j] *= inv;
    for (int j = limit + tid; j < rBlk; j += 256) row[j] = 0.f;
}

// ---------------- router: logits, softmax, top-4, compact lists + tok maps ---
__global__ void router_kernel(const float* __restrict__ h2,
                              const float* __restrict__ gate_w,
                              float* __restrict__ logits_out,
                              int* __restrict__ idxbuf,
                              int* __restrict__ cnt,
                              int* __restrict__ tokmap,
                              float* __restrict__ tokw) {
    int s = blockIdx.x;
    const float* hr = h2 + (long long)s * H;
    __shared__ float red[256][E];
    float p[E];
#pragma unroll
    for (int e = 0; e < E; e++) p[e] = 0.f;
    for (int j = threadIdx.x; j < H; j += 256) {
        float hv = hr[j];
#pragma unroll
        for (int e = 0; e < E; e++) p[e] += hv * gate_w[j * E + e];
    }
#pragma unroll
    for (int e = 0; e < E; e++) red[threadIdx.x][e] = p[e];
    __syncthreads();
    for (int st = 128; st > 0; st >>= 1) {
        if (threadIdx.x < st)
#pragma unroll
            for (int e = 0; e < E; e++) red[threadIdx.x][e] += red[threadIdx.x + st][e];
        __syncthreads();
    }
    if (threadIdx.x == 0) {
        float logit[E];
        float m = -FLT_MAX;
#pragma unroll
        for (int e = 0; e < E; e++) {
            logit[e] = red[0][e];
            logits_out[(long long)s * E + e] = logit[e];
            m = fmaxf(m, logit[e]);
        }
        float sum = 0.f, rw[E];
#pragma unroll
        for (int e = 0; e < E; e++) {
            rw[e] = expf(logit[e] - m);
            sum += rw[e];
        }
        float inv = 1.0f / sum;
#pragma unroll
        for (int e = 0; e < E; e++) rw[e] *= inv;
        bool used[E];
#pragma unroll
        for (int e = 0; e < E; e++) used[e] = false;
        for (int k = 0; k < TOPK; k++) {
            int best = -1;
            float bvv = -FLT_MAX;
            for (int e = 0; e < E; e++)
                if (!used[e] && rw[e] > bvv) { bvv = rw[e]; best = e; }
            used[best] = true;
            int pos = atomicAdd(&cnt[best], 1);
            idxbuf[best * S + pos] = s;
            tokmap[s * TOPK + k] = best * S + pos;
            tokw[s * TOPK + k] = bvv;
        }
    }
}

// ---------------- h2 . sgate ----------------
__global__ void rowdot_kernel(const float* __restrict__ h2,
                              const float* __restrict__ sgate,
                              float* __restrict__ gatev) {
    int s = blockIdx.x;
    const float* hr = h2 + (long long)s * H;
    __shared__ float red[256];
    float acc = 0.f;
    for (int j = threadIdx.x; j < H; j += 256) acc += hr[j] * sgate[j];
    red[threadIdx.x] = acc;
    __syncthreads();
    for (int st = 128; st > 0; st >>= 1) {
        if (threadIdx.x < st) red[threadIdx.x] += red[threadIdx.x + st];
        __syncthreads();
    }
    if (threadIdx.x == 0) gatev[s] = red[0];
}

// ---------------- silu(g)*u, all experts in one launch ----------------
__global__ void silu_mul_expert_kernel(float* __restrict__ gb,
                                       const float* __restrict__ ub,
                                       const int* __restrict__ cnt) {
    int e = blockIdx.y;
    long long i = (long long)blockIdx.x * 256 + threadIdx.x;
    long long lim = (long long)cnt[e] * IE;
    if (i >= lim) return;
    size_t o = (size_t)e * S * IE + i;
    float x = gb[o];
    float sg = 1.0f / (1.0f + expf(-x));
    gb[o] = x * sg * ub[o];
}

// ---------------- silu(g)*u (shared expert) ----------------
__global__ void silu_mul_kernel(float* __restrict__ g, const float* __restrict__ u,
                                long long n) {
    long long i = (long long)blockIdx.x * 256 + threadIdx.x;
    if (i < n) {
        float x = g[i];
        float sg = 1.0f / (1.0f + expf(-x));
        g[i] = x * sg * u[i];
    }
}

// ---------------- final combine: gather 4 expert rows per token ----------------
__global__ void final_kernel(const float* __restrict__ x1,
                             const float* __restrict__ eo,
                             const int* __restrict__ tokmap,
                             const float* __restrict__ tokw,
                             const float* __restrict__ sdwn,
                             const float* __restrict__ gatev,
                             float* __restrict__ out) {
    long long i = (long long)blockIdx.x * 256 + threadIdx.x;
    int s = (int)(i / H);
    int c = (int)(i % H);
    float gv = 1.0f / (1.0f + expf(-gatev[s]));
    float acc = x1[i] + gv * sdwn[i];
#pragma unroll
    for (int j = 0; j < TOPK; j++) {
        int row = tokmap[s * TOPK + j];
        acc += tokw[s * TOPK + j] * eo[(size_t)row * H + c];
    }
    out[i] = acc;
}

// ---------------- host ----------------
extern "C" void kernel_launch(void* const* d_in, const int* in_sizes, int n_in,
                              void* d_out, int out_size) {
    (void)in_sizes; (void)n_in; (void)out_size;
    const float* x     = (const float*)d_in[0];
    const float* ln1   = (const float*)d_in[1];
    const float* ln2   = (const float*)d_in[2];
    const float* wq    = (const float*)d_in[3];
    const float* bq    = (const float*)d_in[4];
    const float* wk    = (const float*)d_in[5];
    const float* bk    = (const float*)d_in[6];
    const float* wv    = (const float*)d_in[7];
    const float* bv    = (const float*)d_in[8];
    const float* wo    = (const float*)d_in[9];
    const float* gatew = (const float*)d_in[10];
    const float* eg    = (const float*)d_in[11];
    const float* eu    = (const float*)d_in[12];
    const float* ed    = (const float*)d_in[13];
    const float* sg    = (const float*)d_in[14];
    const float* su    = (const float*)d_in[15];
    const float* sd    = (const float*)d_in[16];
    const float* sgate = (const float*)d_in[17];
    float* out = (float*)d_out;

    float *h, *q, *k, *v, *scores, *attn, *x1, *h2, *gb, *ub, *eo, *sgb, *sub,
        *sdwn, *gatev, *tokw;
    int *idx, *cnt, *tokmap;
    cudaGetSymbolAddress((void**)&h, g_h);
    cudaGetSymbolAddress((void**)&q, g_q);
    cudaGetSymbolAddress((void**)&k, g_k);
    cudaGetSymbolAddress((void**)&v, g_v);
    cudaGetSymbolAddress((void**)&scores, g_scores);
    cudaGetSymbolAddress((void**)&attn, g_attn);
    cudaGetSymbolAddress((void**)&x1, g_x1);
    cudaGetSymbolAddress((void**)&h2, g_h2);
    cudaGetSymbolAddress((void**)&gb, g_gb);
    cudaGetSymbolAddress((void**)&ub, g_ub);
    cudaGetSymbolAddress((void**)&eo, g_eo);
    cudaGetSymbolAddress((void**)&sgb, g_sgb);
    cudaGetSymbolAddress((void**)&sub, g_sub);
    cudaGetSymbolAddress((void**)&sdwn, g_sdwn);
    cudaGetSymbolAddress((void**)&gatev, g_gatev);
    cudaGetSymbolAddress((void**)&idx, g_idx);
    cudaGetSymbolAddress((void**)&cnt, g_cnt);
    cudaGetSymbolAddress((void**)&tokmap, g_tokmap);
    cudaGetSymbolAddress((void**)&tokw, g_tokw);

    const float ascale = 0.08838834764831845f;

    // 1. h = rmsnorm(x, ln1)
    rmsnorm_kernel<<<S, 256>>>(x, ln1, h);

    // 2. q,k,v = h@W + b (one batched launch, z selects weight/bias/output)
    {
        dim3 grid((NH * D) / 128, S / 128, 3);
        sgemm_kernel<<<grid, 256>>>(h, H, 0, wq, NH * D, 0, q, NH * D, 0, H,
                                    bq, nullptr, 0, 0, 0, 0, 1.0f,
                                    1, wk, wv, bk, bv, k, v);
    }

    // 3. RoPE
    rope_kernel<<<dim3(S, NH), 64>>>(q, k);

    // 4. scores (lower blocks only)
    {
        dim3 grid(S / 128, S / 128, NH);
        sgemm_kernel<<<grid, 256>>>(q, NH * D, D, k, NH * D, D, scores, S,
                                    (long long)S * S, D, nullptr, nullptr, 0,
                                    1, 1, 0, ascale,
                                    0, nullptr, nullptr, nullptr, nullptr,
                                    nullptr, nullptr);
    }

    // 5. causal softmax
    softmax_kernel<<<dim3(S, NH), 256>>>(scores);

    // 6. attn = probs @ v (K bounded at diagonal)
    {
        dim3 grid(D / 128, S / 128, NH);
        sgemm_kernel<<<grid, 256>>>(scores, S, (long long)S * S, v, NH * D, D,
                                    attn, NH * D, D, S, nullptr, nullptr, 0,
                                    0, 0, 1, 1.0f,
                                    0, nullptr, nullptr, nullptr, nullptr,
                                    nullptr, nullptr);
    }

    // 7. x1 = x + attn @ wo
    {
        dim3 grid(H / 128, S / 128, 1);
        sgemm_kernel<<<grid, 256>>>(attn, NH * D, 0, wo, H, 0, x1, H, 0,
                                    NH * D, nullptr, x, H, 0, 0, 0, 1.0f,
                                    0, nullptr, nullptr, nullptr, nullptr,
                                    nullptr, nullptr);
    }

    // 8. h2 = rmsnorm(x1, ln2)
    rmsnorm_kernel<<<S, 256>>>(x1, ln2, h2);

    // 9. router
    cudaMemsetAsync(cnt, 0, E * sizeof(int));
    router_kernel<<<S, 256>>>(h2, gatew, out + (long long)S * H, idx, cnt,
                              tokmap, tokw);

    // 10. MoE gate+up: one launch, z = 2*E (e = z>>1, which = z&1)
    {
        dim3 grid(IE / 128, S / 128, 2 * E);
        mma_gemm_kernel<<<grid, 256>>>(h2, H, 0,
                                       eg, eu, IE, (long long)H * IE,
                                       gb, ub, IE, (long long)S * IE,
                                       S, IE, H, idx, S, cnt, 1);
    }
    // 11. silu across experts
    {
        dim3 grid((unsigned)(((long long)S * IE + 255) / 256), E);
        silu_mul_expert_kernel<<<grid, 256>>>(gb, ub, cnt);
    }
    // 12. MoE down: one launch, z = E
    {
        dim3 grid(H / 128, S / 128, E);
        mma_gemm_kernel<<<grid, 256>>>(gb, IE, (long long)S * IE,
                                       ed, nullptr, H, (long long)IE * H,
                                       eo, nullptr, H, (long long)S * H,
                                       S, H, IE, nullptr, 0, cnt, 0);
    }

    // 13. shared expert: gate+up one launch (z = 2)
    {
        dim3 grid(IS / 128, S / 128, 2);
        mma_gemm_kernel<<<grid, 256>>>(h2, H, 0,
                                       sg, su, IS, 0,
                                       sgb, sub, IS, 0,
                                       S, IS, H, nullptr, 0, nullptr, 1);
    }
    {
        long long n = (long long)S * IS;
        silu_mul_kernel<<<(unsigned)((n + 255) / 256), 256>>>(sgb, sub, n);
    }
    {
        dim3 grid(H / 128, S / 128, 1);
        mma_gemm_kernel<<<grid, 256>>>(sgb, IS, 0,
                                       sd, nullptr, H, 0,
                                       sdwn, nullptr, H, 0,
                                       S, H, IS, nullptr, 0, nullptr, 0);
    }

    // 14. gate scalar
    rowdot_kernel<<<S, 256>>>(h2, sgate, gatev);

    // 15. combine
    final_kernel<<<(S * H) / 256, 256>>>(x1, eo, tokmap, tokw, sdwn, gatev, out);
}

// round 6
// speedup vs baseline: 2.6544x; 1.0027x over previous
#include <cuda_runtime.h>
#include <cuda_bf16.h>
#include <math.h>
#include <float.h>
#include <stdint.h>

#define S 2048
#define H 2048
#define NH 16
#define D 128
#define E 8
#define TOPK 4
#define IE 1408
#define IS 5632

// ---------------- scratch (static device globals; no allocation) --------------
__device__ float g_h[S * H];
__device__ float g_q[S * H];
__device__ float g_k[S * H];
__device__ float g_v[S * H];
__device__ float g_scores[(size_t)NH * S * S];
__device__ float g_attn[S * H];
__device__ float g_x1[S * H];
__device__ float g_h2[S * H];
__device__ float g_ch2[S * H];
__device__ float g_gb[(size_t)E * S * IE];
__device__ float g_ub[(size_t)E * S * IE];
__device__ float g_eo[(size_t)E * S * H];
__device__ float g_sgb[S * IS];
__device__ float g_sub[S * IS];
__device__ float g_sdwn[S * H];
__device__ float g_gatev[S];
__device__ int g_idx[E * S];
__device__ int g_cnt[E];
__device__ int g_tokmap[S * TOPK];
__device__ float g_tokw[S * TOPK];
// tf32-preconverted weights
__device__ float g_ceg[(size_t)E * H * IE];
__device__ float g_ceu[(size_t)E * H * IE];
__device__ float g_ced[(size_t)E * IE * H];
__device__ float g_csg[(size_t)H * IS];
__device__ float g_csu[(size_t)H * IS];
__device__ float g_csd[(size_t)IS * H];

// ================= helpers =================
__device__ __forceinline__ uint32_t smem_to_u32(const void* p) {
    uint32_t a;
    asm("{ .reg .u64 t; cvta.to.shared.u64 t, %1; cvt.u32.u64 %0, t; }"
        : "=r"(a) : "l"(p));
    return a;
}
__device__ __forceinline__ float f2tf32f(float f) {
    uint32_t r;
    asm("cvt.rna.tf32.f32 %0, %1;" : "=r"(r) : "f"(f));
    return __uint_as_float(r);
}
__device__ __forceinline__ void mma_tf32(float* d, const uint32_t* a,
                                         const uint32_t* b) {
    asm volatile(
        "mma.sync.aligned.m16n8k8.row.col.f32.tf32.tf32.f32 "
        "{%0,%1,%2,%3}, {%4,%5,%6,%7}, {%8,%9}, {%0,%1,%2,%3};"
        : "+f"(d[0]), "+f"(d[1]), "+f"(d[2]), "+f"(d[3])
        : "r"(a[0]), "r"(a[1]), "r"(a[2]), "r"(a[3]), "r"(b[0]), "r"(b[1]));
}
__device__ __forceinline__ void cp_async16(uint32_t dst, const void* src) {
    asm volatile("cp.async.ca.shared.global [%0], [%1], 16;"
                 :: "r"(dst), "l"(src));
}

// ================= tf32 mma GEMM v2: CTA 128x256, warp 64x64, cp.async ========
// Inputs must already be tf32-rounded fp32. B is [K][N] row-major.
#define APADF 20
#define BPADF 264
#define A_B0 0u
#define A_B1 10240u
#define B_B0 20480u
#define B_BSZ 16896u
#define MMA_SMEM (20480 + 2 * 16896)

__global__ __launch_bounds__(256, 1)
void mma_gemm_kernel(const float* __restrict__ A, int lda, long long aStrE,
                     const float* __restrict__ B0, const float* __restrict__ B1,
                     int ldb, long long bStrE,
                     float* __restrict__ C0, float* __restrict__ C1,
                     int ldc, long long cStrE,
                     int M, int N, int K,
                     const int* __restrict__ gidxBase, int gidxStr,
                     const int* __restrict__ cntBase, int eShift) {
    extern __shared__ char smem[];
    const uint32_t sb = smem_to_u32(smem);
    const int z = blockIdx.z;
    const int e = z >> eShift;
    const int which = z & ((1 << eShift) - 1);
    const float* B = (which ? B1 : B0) + (long long)e * bStrE;
    float* C = (which ? C1 : C0) + (long long)e * cStrE;
    A += (long long)e * aStrE;

    const int cnt = cntBase ? cntBase[e] : M;
    const int mEff = min(M, cnt);
    const int row0 = blockIdx.y * 128;
    const int col0 = blockIdx.x * 256;
    if (row0 >= mEff) return;
    const int* gidx = gidxBase ? gidxBase + (long long)e * gidxStr : nullptr;

    const int tid = threadIdx.x;
    const int wid = tid >> 5;
    const int lane = tid & 31;
    const int g = lane >> 2;
    const int t4 = lane & 3;
    const int warpM = wid >> 2;  // 0..1
    const int warpN = wid & 3;   // 0..3

    // ---- cp.async task plans ----
    // A: 128x16 floats -> 512 float4 -> 2 per thread
    const float* aG[2];
    uint32_t aS[2];
#pragma unroll
    for (int j = 0; j < 2; j++) {
        int u = tid + 256 * j;
        int m = u >> 2, c4 = u & 3;
        int arow = row0 + m;
        int src;
        if (gidx) src = (arow < cnt) ? gidx[arow] : 0;
        else src = min(arow, M - 1);
        aG[j] = A + (size_t)src * lda + c4 * 4;
        aS[j] = sb + A_B0 + (uint32_t)(m * APADF + c4 * 4) * 4u;
    }
    // B: 16 k-rows x 256 cols -> 1024 float4 -> 4 per thread (k-major smem)
    const float* bG[4];
    uint32_t bS[4];
#pragma unroll
    for (int j = 0; j < 4; j++) {
        int u = tid + 256 * j;
        int kk = u & 15, n4 = u >> 4;
        int bcol = col0 + n4 * 4;
        if (bcol > N - 4) bcol = N - 4;
        bG[j] = B + (size_t)kk * ldb + bcol;
        bS[j] = sb + B_B0 + (uint32_t)(kk * BPADF + n4 * 4) * 4u;
    }

    float acc[4][8][4];
#pragma unroll
    for (int mt = 0; mt < 4; mt++)
#pragma unroll
        for (int nt = 0; nt < 8; nt++)
#pragma unroll
            for (int r = 0; r < 4; r++) acc[mt][nt][r] = 0.f;

    const int nT = K / 16;

#define ISSUE(i)                                                         \
    do {                                                                 \
        int _buf = (i) & 1;                                              \
        int _k0 = (i) * 16;                                              \
        uint32_t _ao = _buf ? (A_B1 - A_B0) : 0u;                        \
        uint32_t _bo = _buf ? B_BSZ : 0u;                                \
        cp_async16(aS[0] + _ao, aG[0] + _k0);                            \
        cp_async16(aS[1] + _ao, aG[1] + _k0);                            \
        cp_async16(bS[0] + _bo, bG[0] + (size_t)_k0 * ldb);              \
        cp_async16(bS[1] + _bo, bG[1] + (size_t)_k0 * ldb);              \
        cp_async16(bS[2] + _bo, bG[2] + (size_t)_k0 * ldb);              \
        cp_async16(bS[3] + _bo, bG[3] + (size_t)_k0 * ldb);              \
        asm volatile("cp.async.commit_group;");                          \
    } while (0)

    ISSUE(0);
    if (nT > 1) ISSUE(1);

    for (int i = 0; i < nT; i++) {
        if (i + 1 < nT)
            asm volatile("cp.async.wait_group 1;");
        else
            asm volatile("cp.async.wait_group 0;");
        __syncthreads();
        const uint32_t* Asb =
            (const uint32_t*)(smem + ((i & 1) ? A_B1 : A_B0));
        const uint32_t* Bsb =
            (const uint32_t*)(smem + B_B0 + ((i & 1) ? B_BSZ : 0u));
#pragma unroll
        for (int kk = 0; kk < 16; kk += 8) {
            uint32_t a[4][4], b[8][2];
#pragma unroll
            for (int mt = 0; mt < 4; mt++) {
                int mrow = warpM * 64 + mt * 16;
                a[mt][0] = Asb[(mrow + g) * APADF + kk + t4];
                a[mt][1] = Asb[(mrow + g + 8) * APADF + kk + t4];
                a[mt][2] = Asb[(mrow + g) * APADF + kk + t4 + 4];
                a[mt][3] = Asb[(mrow + g + 8) * APADF + kk + t4 + 4];
            }
#pragma unroll
            for (int nt = 0; nt < 8; nt++) {
                int ncol = warpN * 64 + nt * 8;
                b[nt][0] = Bsb[(kk + t4) * BPADF + ncol + g];
                b[nt][1] = Bsb[(kk + t4 + 4) * BPADF + ncol + g];
            }
#pragma unroll
            for (int mt = 0; mt < 4; mt++)
#pragma unroll
                for (int nt = 0; nt < 8; nt++)
                    mma_tf32(acc[mt][nt], a[mt], b[nt]);
        }
        __syncthreads();
        if (i + 2 < nT) ISSUE(i + 2);
    }
#undef ISSUE

    // epilogue
#pragma unroll
    for (int mt = 0; mt < 4; mt++) {
        int rBase = row0 + warpM * 64 + mt * 16 + g;
#pragma unroll
        for (int half = 0; half < 2; half++) {
            int r = rBase + half * 8;
            if (r >= mEff) continue;
            float* cp = C + (size_t)r * ldc;
#pragma unroll
            for (int nt = 0; nt < 8; nt++) {
                int col = col0 + warpN * 64 + nt * 8 + t4 * 2;
                if (col < N) {
                    cp[col] = acc[mt][nt][half * 2 + 0];
                    cp[col + 1] = acc[mt][nt][half * 2 + 1];
                }
            }
        }
    }
}

// ---------------- bulk tf32 rounding ----------------
__global__ void cvt_kernel(const float4* __restrict__ src,
                           float4* __restrict__ dst, long long n4) {
    long long i = (long long)blockIdx.x * 256 + threadIdx.x;
    if (i < n4) {
        float4 v = src[i];
        v.x = f2tf32f(v.x);
        v.y = f2tf32f(v.y);
        v.z = f2tf32f(v.z);
        v.w = f2tf32f(v.w);
        dst[i] = v;
    }
}

// ---------------- RMSNorm ----------------
__global__ void rmsnorm_kernel(const float* __restrict__ x,
                               const float* __restrict__ w,
                               float* __restrict__ out) {
    const float* xr = x + (long long)blockIdx.x * H;
    float* orow = out + (long long)blockIdx.x * H;
    __shared__ float red[256];
    float s = 0.f;
    for (int j = threadIdx.x; j < H; j += 256) {
        float v = xr[j];
        s += v * v;
    }
    red[threadIdx.x] = s;
    __syncthreads();
    for (int st = 128; st > 0; st >>= 1) {
        if (threadIdx.x < st) red[threadIdx.x] += red[threadIdx.x + st];
        __syncthreads();
    }
    float inv = 1.0f / sqrtf(red[0] / (float)H + 1e-6f);
    for (int j = threadIdx.x; j < H; j += 256) orow[j] = w[j] * xr[j] * inv;
}

// ---------------- fp32 SGEMM (upstream of router) ----------------
__global__ __launch_bounds__(256, 2)
void sgemm_kernel(const float* __restrict__ A, int lda, long long sA,
                  const float* __restrict__ B, int ldb, long long sB,
                  float* __restrict__ C, int ldc, long long sC,
                  int K,
                  const float* __restrict__ bias,
                  const float* __restrict__ residual, int ldr,
                  int transB, int causal, int kLimit, float scale,
                  int selMode,
                  const float* B1, const float* B2,
                  const float* bias1, const float* bias2,
                  float* C1, float* C2) {
    __shared__ __align__(16) float As[2][8][128];
    __shared__ __align__(16) float Bs[2][8][128];

    const int bz = blockIdx.z;
    if (selMode) {
        if (bz == 1) { B = B1; bias = bias1; C = C1; }
        else if (bz == 2) { B = B2; bias = bias2; C = C2; }
    } else {
        A += (long long)bz * sA;
        B += (long long)bz * sB;
        C += (long long)bz * sC;
    }

    const int row0 = blockIdx.y * 128;
    const int col0 = blockIdx.x * 128;
    if (causal && col0 > row0) return;
    int Keff = kLimit ? min(K, row0 + 128) : K;

    const int tid = threadIdx.x;
    const int trow = (tid >> 4) * 8;
    const int tcol = (tid & 15) * 8;

    const int aRow = tid >> 1;
    const int aCol = (tid & 1) * 4;
    const int bRow = tid >> 5;
    const int bCol = (tid & 31) * 4;

    const float* Aptr = A + (long long)(row0 + aRow) * lda + aCol;
    const float* BptrNN = B + (long long)bRow * ldb + col0 + bCol;
    const float* BptrNT = B + (long long)(col0 + aRow) * ldb + aCol;

    unsigned long long acc[4][8];
#pragma unroll
    for (int i = 0; i < 4; i++)
#pragma unroll
        for (int j = 0; j < 8; j++) acc[i][j] = 0ull;

    float4 av = *reinterpret_cast<const float4*>(Aptr);
    float4 bv = transB ? *reinterpret_cast<const float4*>(BptrNT)
                       : *reinterpret_cast<const float4*>(BptrNN);
    As[0][aCol + 0][aRow] = av.x;
    As[0][aCol + 1][aRow] = av.y;
    As[0][aCol + 2][aRow] = av.z;
    As[0][aCol + 3][aRow] = av.w;
    if (transB) {
        Bs[0][aCol + 0][aRow] = bv.x;
        Bs[0][aCol + 1][aRow] = bv.y;
        Bs[0][aCol + 2][aRow] = bv.z;
        Bs[0][aCol + 3][aRow] = bv.w;
    } else {
        *reinterpret_cast<float4*>(&Bs[0][bRow][bCol]) = bv;
    }
    __syncthreads();

    int buf = 0;
    for (int k0 = 0; k0 < Keff; k0 += 8) {
        const bool more = (k0 + 8) < Keff;
        if (more) {
            av = *reinterpret_cast<const float4*>(Aptr + k0 + 8);
            bv = transB
                     ? *reinterpret_cast<const float4*>(BptrNT + k0 + 8)
                     : *reinterpret_cast<const float4*>(BptrNN + (long long)(k0 + 8) * ldb);
        }
#pragma unroll
        for (int kk = 0; kk < 8; kk++) {
            ulonglong2 a01 = *reinterpret_cast<const ulonglong2*>(&As[buf][kk][trow]);
            ulonglong2 a23 = *reinterpret_cast<const ulonglong2*>(&As[buf][kk][trow + 4]);
            float4 b0 = *reinterpret_cast<const float4*>(&Bs[buf][kk][tcol]);
            float4 b1 = *reinterpret_cast<const float4*>(&Bs[buf][kk][tcol + 4]);
            unsigned long long ap[4];
            ap[0] = a01.x; ap[1] = a01.y; ap[2] = a23.x; ap[3] = a23.y;
            float bvals[8];
            bvals[0] = b0.x; bvals[1] = b0.y; bvals[2] = b0.z; bvals[3] = b0.w;
            bvals[4] = b1.x; bvals[5] = b1.y; bvals[6] = b1.z; bvals[7] = b1.w;
#pragma unroll
            for (int j = 0; j < 8; j++) {
                unsigned long long bp;
                asm("mov.b64 %0, {%1, %1};" : "=l"(bp) : "f"(bvals[j]));
#pragma unroll
                for (int i2 = 0; i2 < 4; i2++) {
                    asm("fma.rn.f32x2 %0, %1, %2, %0;"
                        : "+l"(acc[i2][j]) : "l"(ap[i2]), "l"(bp));
                }
            }
        }
        if (more) {
            int nb = buf ^ 1;
            As[nb][aCol + 0][aRow] = av.x;
            As[nb][aCol + 1][aRow] = av.y;
            As[nb][aCol + 2][aRow] = av.z;
            As[nb][aCol + 3][aRow] = av.w;
            if (transB) {
                Bs[nb][aCol + 0][aRow] = bv.x;
                Bs[nb][aCol + 1][aRow] = bv.y;
                Bs[nb][aCol + 2][aRow] = bv.z;
                Bs[nb][aCol + 3][aRow] = bv.w;
            } else {
                *reinterpret_cast<float4*>(&Bs[nb][bRow][bCol]) = bv;
            }
        }
        __syncthreads();
        buf ^= 1;
    }

#pragma unroll
    for (int i2 = 0; i2 < 4; i2++) {
#pragma unroll
        for (int j = 0; j < 8; j++) {
            float lo, hi;
            asm("mov.b64 {%0, %1}, %2;" : "=f"(lo), "=f"(hi) : "l"(acc[i2][j]));
            int c = col0 + tcol + j;
#pragma unroll
            for (int half = 0; half < 2; half++) {
                int r = row0 + trow + 2 * i2 + half;
                float v = (half == 0 ? lo : hi) * scale;
                if (bias) v += bias[c];
                if (residual) v += residual[(long long)r * ldr + c];
                C[(long long)r * ldc + c] = v;
            }
        }
    }
}

// ---------------- RoPE ----------------
__global__ void rope_kernel(float* __restrict__ q, float* __restrict__ k) {
    int s = blockIdx.x;
    int h = blockIdx.y;
    int j = threadIdx.x;
    double invd = pow(1.0e6, -(double)j / 64.0);
    float ang = (float)((double)s * invd);
    float c = cosf(ang), sn = sinf(ang);
    long long base = ((long long)s * NH + h) * D;
    float q1 = q[base + j], q2 = q[base + j + 64];
    q[base + j] = q1 * c - q2 * sn;
    q[base + j + 64] = q2 * c + q1 * sn;
    float k1 = k[base + j], k2 = k[base + j + 64];
    k[base + j] = k1 * c - k2 * sn;
    k[base + j + 64] = k2 * c + k1 * sn;
}

// ---------------- causal row softmax ----------------
__global__ void softmax_kernel(float* __restrict__ scores) {
    int r = blockIdx.x;
    float* row = scores + ((long long)blockIdx.y * S + r) * S;
    const int limit = r + 1;
    const int rBlk = ((r >> 7) + 1) << 7;
    __shared__ float red[256];
    int tid = threadIdx.x;
    float m = -FLT_MAX;
    for (int j = tid; j < limit; j += 256) m = fmaxf(m, row[j]);
    red[tid] = m;
    __syncthreads();
    for (int st = 128; st > 0; st >>= 1) {
        if (tid < st) red[tid] = fmaxf(red[tid], red[tid + st]);
        __syncthreads();
    }
    m = red[0];
    __syncthreads();
    float sum = 0.f;
    for (int j = tid; j < limit; j += 256) {
        float e = expf(row[j] - m);
        row[j] = e;
        sum += e;
    }
    red[tid] = sum;
    __syncthreads();
    for (int st = 128; st > 0; st >>= 1) {
        if (tid < st) red[tid] += red[tid + st];
        __syncthreads();
    }
    float inv = 1.0f / red[0];
    for (int j = tid; j < limit; j += 256) row[j] *= inv;
    for (int j = limit + tid; j < rBlk; j += 256) row[j] = 0.f;
}

// ---------------- router ----------------
__global__ void router_kernel(const float* __restrict__ h2,
                              const float* __restrict__ gate_w,
                              float* __restrict__ logits_out,
                              int* __restrict__ idxbuf,
                              int* __restrict__ cnt,
                              int* __restrict__ tokmap,
                              float* __restrict__ tokw) {
    int s = blockIdx.x;
    const float* hr = h2 + (long long)s * H;
    __shared__ float red[256][E];
    float p[E];
#pragma unroll
    for (int e = 0; e < E; e++) p[e] = 0.f;
    for (int j = threadIdx.x; j < H; j += 256) {
        float hv = hr[j];
#pragma unroll
        for (int e = 0; e < E; e++) p[e] += hv * gate_w[j * E + e];
    }
#pragma unroll
    for (int e = 0; e < E; e++) red[threadIdx.x][e] = p[e];
    __syncthreads();
    for (int st = 128; st > 0; st >>= 1) {
        if (threadIdx.x < st)
#pragma unroll
            for (int e = 0; e < E; e++) red[threadIdx.x][e] += red[threadIdx.x + st][e];
        __syncthreads();
    }
    if (threadIdx.x == 0) {
        float logit[E];
        float m = -FLT_MAX;
#pragma unroll
        for (int e = 0; e < E; e++) {
            logit[e] = red[0][e];
            logits_out[(long long)s * E + e] = logit[e];
            m = fmaxf(m, logit[e]);
        }
        float sum = 0.f, rw[E];
#pragma unroll
        for (int e = 0; e < E; e++) {
            rw[e] = expf(logit[e] - m);
            sum += rw[e];
        }
        float inv = 1.0f / sum;
#pragma unroll
        for (int e = 0; e < E; e++) rw[e] *= inv;
        bool used[E];
#pragma unroll
        for (int e = 0; e < E; e++) used[e] = false;
        for (int k = 0; k < TOPK; k++) {
            int best = -1;
            float bvv = -FLT_MAX;
            for (int e = 0; e < E; e++)
                if (!used[e] && rw[e] > bvv) { bvv = rw[e]; best = e; }
            used[best] = true;
            int pos = atomicAdd(&cnt[best], 1);
            idxbuf[best * S + pos] = s;
            tokmap[s * TOPK + k] = best * S + pos;
            tokw[s * TOPK + k] = bvv;
        }
    }
}

// ---------------- h2 . sgate ----------------
__global__ void rowdot_kernel(const float* __restrict__ h2,
                              const float* __restrict__ sgate,
                              float* __restrict__ gatev) {
    int s = blockIdx.x;
    const float* hr = h2 + (long long)s * H;
    __shared__ float red[256];
    float acc = 0.f;
    for (int j = threadIdx.x; j < H; j += 256) acc += hr[j] * sgate[j];
    red[threadIdx.x] = acc;
    __syncthreads();
    for (int st = 128; st > 0; st >>= 1) {
        if (threadIdx.x < st) red[threadIdx.x] += red[threadIdx.x + st];
        __syncthreads();
    }
    if (threadIdx.x == 0) gatev[s] = red[0];
}

// ---------------- silu(g)*u, experts (output tf32-rounded) ----------------
__global__ void silu_mul_expert_kernel(float* __restrict__ gb,
                                       const float* __restrict__ ub,
                                       const int* __restrict__ cnt) {
    int e = blockIdx.y;
    long long i = (long long)blockIdx.x * 256 + threadIdx.x;
    long long lim = (long long)cnt[e] * IE;
    if (i >= lim) return;
    size_t o = (size_t)e * S * IE + i;
    float x = gb[o];
    float sg = 1.0f / (1.0f + expf(-x));
    gb[o] = f2tf32f(x * sg * ub[o]);
}

// ---------------- silu(g)*u shared (output tf32-rounded) ----------------
__global__ void silu_mul_kernel(float* __restrict__ g, const float* __restrict__ u,
                                long long n) {
    long long i = (long long)blockIdx.x * 256 + threadIdx.x;
    if (i < n) {
        float x = g[i];
        float sg = 1.0f / (1.0f + expf(-x));
        g[i] = f2tf32f(x * sg * u[i]);
    }
}

// ---------------- final combine ----------------
__global__ void final_kernel(const float* __restrict__ x1,
                             const float* __restrict__ eo,
                             const int* __restrict__ tokmap,
                             const float* __restrict__ tokw,
                             const float* __restrict__ sdwn,
                             const float* __restrict__ gatev,
                             float* __restrict__ out) {
    long long i = (long long)blockIdx.x * 256 + threadIdx.x;
    int s = (int)(i / H);
    int c = (int)(i % H);
    float gv = 1.0f / (1.0f + expf(-gatev[s]));
    float acc = x1[i] + gv * sdwn[i];
#pragma unroll
    for (int j = 0; j < TOPK; j++) {
        int row = tokmap[s * TOPK + j];
        acc += tokw[s * TOPK + j] * eo[(size_t)row * H + c];
    }
    out[i] = acc;
}

// ---------------- host ----------------
static void launch_cvt(const float* src, float* dst, long long n) {
    long long n4 = n / 4;
    cvt_kernel<<<(unsigned)((n4 + 255) / 256), 256>>>((const float4*)src,
                                                      (float4*)dst, n4);
}

static void launch_mma(const float* A, int lda, long long aStrE,
                       const float* B0, const float* B1, int ldb, long long bStrE,
                       float* C0, float* C1, int ldc, long long cStrE,
                       int M, int N, int K,
                       const int* gidx, int gstr, const int* cnt, int eShift,
                       int nz) {
    dim3 grid((N + 255) / 256, (M + 127) / 128, nz);
    mma_gemm_kernel<<<grid, 256, MMA_SMEM>>>(A, lda, aStrE, B0, B1, ldb, bStrE,
                                             C0, C1, ldc, cStrE, M, N, K,
                                             gidx, gstr, cnt, eShift);
}

extern "C" void kernel_launch(void* const* d_in, const int* in_sizes, int n_in,
                              void* d_out, int out_size) {
    (void)in_sizes; (void)n_in; (void)out_size;
    const float* x     = (const float*)d_in[0];
    const float* ln1   = (const float*)d_in[1];
    const float* ln2   = (const float*)d_in[2];
    const float* wq    = (const float*)d_in[3];
    const float* bq    = (const float*)d_in[4];
    const float* wk    = (const float*)d_in[5];
    const float* bk    = (const float*)d_in[6];
    const float* wv    = (const float*)d_in[7];
    const float* bv    = (const float*)d_in[8];
    const float* wo    = (const float*)d_in[9];
    const float* gatew = (const float*)d_in[10];
    const float* eg    = (const float*)d_in[11];
    const float* eu    = (const float*)d_in[12];
    const float* ed    = (const float*)d_in[13];
    const float* sg    = (const float*)d_in[14];
    const float* su    = (const float*)d_in[15];
    const float* sd    = (const float*)d_in[16];
    const float* sgate = (const float*)d_in[17];
    float* out = (float*)d_out;

    cudaFuncSetAttribute(mma_gemm_kernel,
                         cudaFuncAttributeMaxDynamicSharedMemorySize, MMA_SMEM);

    float *h, *q, *k, *v, *scores, *attn, *x1, *h2, *ch2, *gb, *ub, *eo, *sgb,
        *sub, *sdwn, *gatev, *tokw;
    float *ceg, *ceu, *ced, *csg, *csu, *csd;
    int *idx, *cnt, *tokmap;
    cudaGetSymbolAddress((void**)&h, g_h);
    cudaGetSymbolAddress((void**)&q, g_q);
    cudaGetSymbolAddress((void**)&k, g_k);
    cudaGetSymbolAddress((void**)&v, g_v);
    cudaGetSymbolAddress((void**)&scores, g_scores);
    cudaGetSymbolAddress((void**)&attn, g_attn);
    cudaGetSymbolAddress((void**)&x1, g_x1);
    cudaGetSymbolAddress((void**)&h2, g_h2);
    cudaGetSymbolAddress((void**)&ch2, g_ch2);
    cudaGetSymbolAddress((void**)&gb, g_gb);
    cudaGetSymbolAddress((void**)&ub, g_ub);
    cudaGetSymbolAddress((void**)&eo, g_eo);
    cudaGetSymbolAddress((void**)&sgb, g_sgb);
    cudaGetSymbolAddress((void**)&sub, g_sub);
    cudaGetSymbolAddress((void**)&sdwn, g_sdwn);
    cudaGetSymbolAddress((void**)&gatev, g_gatev);
    cudaGetSymbolAddress((void**)&idx, g_idx);
    cudaGetSymbolAddress((void**)&cnt, g_cnt);
    cudaGetSymbolAddress((void**)&tokmap, g_tokmap);
    cudaGetSymbolAddress((void**)&tokw, g_tokw);
    cudaGetSymbolAddress((void**)&ceg, g_ceg);
    cudaGetSymbolAddress((void**)&ceu, g_ceu);
    cudaGetSymbolAddress((void**)&ced, g_ced);
    cudaGetSymbolAddress((void**)&csg, g_csg);
    cudaGetSymbolAddress((void**)&csu, g_csu);
    cudaGetSymbolAddress((void**)&csd, g_csd);

    const float ascale = 0.08838834764831845f;

    // 0. pre-round weights to tf32
    launch_cvt(eg, ceg, (long long)E * H * IE);
    launch_cvt(eu, ceu, (long long)E * H * IE);
    launch_cvt(ed, ced, (long long)E * IE * H);
    launch_cvt(sg, csg, (long long)H * IS);
    launch_cvt(su, csu, (long long)H * IS);
    launch_cvt(sd, csd, (long long)IS * H);

    // 1. h = rmsnorm(x, ln1)
    rmsnorm_kernel<<<S, 256>>>(x, ln1, h);

    // 2. q,k,v (batched fp32)
    {
        dim3 grid((NH * D) / 128, S / 128, 3);
        sgemm_kernel<<<grid, 256>>>(h, H, 0, wq, NH * D, 0, q, NH * D, 0, H,
                                    bq, nullptr, 0, 0, 0, 0, 1.0f,
                                    1, wk, wv, bk, bv, k, v);
    }

    // 3. RoPE
    rope_kernel<<<dim3(S, NH), 64>>>(q, k);

    // 4. scores
    {
        dim3 grid(S / 128, S / 128, NH);
        sgemm_kernel<<<grid, 256>>>(q, NH * D, D, k, NH * D, D, scores, S,
                                    (long long)S * S, D, nullptr, nullptr, 0,
                                    1, 1, 0, ascale,
                                    0, nullptr, nullptr, nullptr, nullptr,
                                    nullptr, nullptr);
    }

    // 5. softmax
    softmax_kernel<<<dim3(S, NH), 256>>>(scores);

    // 6. attn = probs @ v
    {
        dim3 grid(D / 128, S / 128, NH);
        sgemm_kernel<<<grid, 256>>>(scores, S, (long long)S * S, v, NH * D, D,
                                    attn, NH * D, D, S, nullptr, nullptr, 0,
                                    0, 0, 1, 1.0f,
                                    0, nullptr, nullptr, nullptr, nullptr,
                                    nullptr, nullptr);
    }

    // 7. x1 = x + attn @ wo
    {
        dim3 grid(H / 128, S / 128, 1);
        sgemm_kernel<<<grid, 256>>>(attn, NH * D, 0, wo, H, 0, x1, H, 0,
                                    NH * D, nullptr, x, H, 0, 0, 0, 1.0f,
                                    0, nullptr, nullptr, nullptr, nullptr,
                                    nullptr, nullptr);
    }

    // 8. h2 = rmsnorm(x1, ln2); tf32 copy for MoE A
    rmsnorm_kernel<<<S, 256>>>(x1, ln2, h2);
    launch_cvt(h2, ch2, (long long)S * H);

    // 9. router (exact h2)
    cudaMemsetAsync(cnt, 0, E * sizeof(int));
    router_kernel<<<S, 256>>>(h2, gatew, out + (long long)S * H, idx, cnt,
                              tokmap, tokw);

    // 10. MoE gate+up (z = 2E)
    launch_mma(ch2, H, 0, ceg, ceu, IE, (long long)H * IE,
               gb, ub, IE, (long long)S * IE, S, IE, H, idx, S, cnt, 1, 2 * E);

    // 11. silu (+tf32 round)
    {
        dim3 grid((unsigned)(((long long)S * IE + 255) / 256), E);
        silu_mul_expert_kernel<<<grid, 256>>>(gb, ub, cnt);
    }

    // 12. MoE down (z = E)
    launch_mma(gb, IE, (long long)S * IE, ced, nullptr, H, (long long)IE * H,
               eo, nullptr, H, (long long)S * H, S, H, IE, nullptr, 0, cnt, 0, E);

    // 13. shared expert
    launch_mma(ch2, H, 0, csg, csu, IS, 0, sgb, sub, IS, 0, S, IS, H,
               nullptr, 0, nullptr, 1, 2);
    {
        long long n = (long long)S * IS;
        silu_mul_kernel<<<(unsigned)((n + 255) / 256), 256>>>(sgb, sub, n);
    }
    launch_mma(sgb, IS, 0, csd, nullptr, H, 0, sdwn, nullptr, H, 0, S, H, IS,
               nullptr, 0, nullptr, 0, 1);

    // 14. gate scalar
    rowdot_kernel<<<S, 256>>>(h2, sgate, gatev);

    // 15. combine
    final_kernel<<<(S * H) / 256, 256>>>(x1, eo, tokmap, tokw, sdwn, gatev, out);
}

// round 7
// speedup vs baseline: 3.3985x; 1.2803x over previous
#include <cuda_runtime.h>
#include <cuda_bf16.h>
#include <math.h>
#include <float.h>
#include <stdint.h>

#define S 2048
#define H 2048
#define NH 16
#define D 128
#define E 8
#define TOPK 4
#define IE 1408
#define IS 5632

// ---------------- scratch (static device globals; no allocation) --------------
__device__ float g_h[S * H];
__device__ float g_q[S * H];
__device__ float g_k[S * H];
__device__ float g_v[S * H];
__device__ float g_scores[(size_t)NH * S * S];
__device__ float g_attn[S * H];
__device__ float g_x1[S * H];
__device__ float g_h2[S * H];
__device__ float g_ch2[S * H];
__device__ float g_gb[(size_t)E * S * IE];
__device__ float g_ub[(size_t)E * S * IE];
__device__ float g_eo[(size_t)E * S * H];
__device__ float g_sgb[S * IS];
__device__ float g_sub[S * IS];
__device__ float g_sdwn[S * H];
__device__ float g_gatev[S];
__device__ int g_idx[E * S];
__device__ int g_cnt[E];
__device__ int g_tokmap[S * TOPK];
__device__ float g_tokw[S * TOPK];
// tf32-preconverted weights
__device__ float g_ceg[(size_t)E * H * IE];
__device__ float g_ceu[(size_t)E * H * IE];
__device__ float g_ced[(size_t)E * IE * H];
__device__ float g_csg[(size_t)H * IS];
__device__ float g_csu[(size_t)H * IS];
__device__ float g_csd[(size_t)IS * H];

// ================= helpers =================
__device__ __forceinline__ uint32_t smem_to_u32(const void* p) {
    uint32_t a;
    asm("{ .reg .u64 t; cvta.to.shared.u64 t, %1; cvt.u32.u64 %0, t; }"
        : "=r"(a) : "l"(p));
    return a;
}
__device__ __forceinline__ float f2tf32f(float f) {
    uint32_t r;
    asm("cvt.rna.tf32.f32 %0, %1;" : "=r"(r) : "f"(f));
    return __uint_as_float(r);
}
__device__ __forceinline__ void mma_tf32(float* d, const uint32_t* a,
                                         const uint32_t* b) {
    asm volatile(
        "mma.sync.aligned.m16n8k8.row.col.f32.tf32.tf32.f32 "
        "{%0,%1,%2,%3}, {%4,%5,%6,%7}, {%8,%9}, {%0,%1,%2,%3};"
        : "+f"(d[0]), "+f"(d[1]), "+f"(d[2]), "+f"(d[3])
        : "r"(a[0]), "r"(a[1]), "r"(a[2]), "r"(a[3]), "r"(b[0]), "r"(b[1]));
}
__device__ __forceinline__ void cp_async16(uint32_t dst, const void* src) {
    asm volatile("cp.async.ca.shared.global [%0], [%1], 16;"
                 :: "r"(dst), "l"(src));
}

// ================= tf32 mma GEMM v3 ==========================================
// CTA 128x128, 128 threads (4 warps @ 64x64), 4-stage cp.async ring, 2 CTA/SM.
// Inputs must already be tf32-rounded fp32. B is [K][N] row-major. N%128==0.
#define APADF 20
#define BPADF 136
#define A_STAGE_B (128 * APADF * 4)  // 10240
#define B_STAGE_B (16 * BPADF * 4)   // 8704
#define STAGE_B (A_STAGE_B + B_STAGE_B)
#define NSTAGE 4
#define MMA_SMEM (STAGE_B * NSTAGE)  // 75776

__global__ __launch_bounds__(128, 2)
void mma_gemm_kernel(const float* __restrict__ A, int lda, long long aStrE,
                     const float* __restrict__ B0, const float* __restrict__ B1,
                     int ldb, long long bStrE,
                     float* __restrict__ C0, float* __restrict__ C1,
                     int ldc, long long cStrE,
                     int M, int N, int K,
                     const int* __restrict__ gidxBase, int gidxStr,
                     const int* __restrict__ cntBase, int eShift) {
    extern __shared__ char smem[];
    const uint32_t sb = smem_to_u32(smem);
    const int z = blockIdx.z;
    const int e = z >> eShift;
    const int which = z & ((1 << eShift) - 1);
    const float* B = (which ? B1 : B0) + (long long)e * bStrE;
    float* C = (which ? C1 : C0) + (long long)e * cStrE;
    A += (long long)e * aStrE;

    const int cnt = cntBase ? cntBase[e] : M;
    const int mEff = min(M, cnt);
    const int row0 = blockIdx.y * 128;
    const int col0 = blockIdx.x * 128;
    if (row0 >= mEff) return;
    const int* gidx = gidxBase ? gidxBase + (long long)e * gidxStr : nullptr;

    const int tid = threadIdx.x;
    const int wid = tid >> 5;
    const int lane = tid & 31;
    const int g = lane >> 2;
    const int t4 = lane & 3;
    const int warpM = wid >> 1;  // 0..1
    const int warpN = wid & 1;   // 0..1

    // ---- cp.async task plans (4 A-f4 + 4 B-f4 per thread per stage) ----
    const float* aG[4];
    uint32_t aS[4];
#pragma unroll
    for (int j = 0; j < 4; j++) {
        int u = tid + 128 * j;
        int m = u >> 2, c4 = u & 3;
        int arow = row0 + m;
        int src;
        if (gidx) src = (arow < cnt) ? gidx[arow] : 0;
        else src = min(arow, M - 1);
        aG[j] = A + (size_t)src * lda + c4 * 4;
        aS[j] = sb + (uint32_t)(m * APADF + c4 * 4) * 4u;
    }
    const float* bG[4];
    uint32_t bS[4];
#pragma unroll
    for (int j = 0; j < 4; j++) {
        int u = tid + 128 * j;
        int n4 = u & 31, kk = u >> 5;
        bG[j] = B + (size_t)kk * ldb + col0 + n4 * 4;
        bS[j] = sb + A_STAGE_B + (uint32_t)(kk * BPADF + n4 * 4) * 4u;
    }

    float acc[4][8][4];
#pragma unroll
    for (int mt = 0; mt < 4; mt++)
#pragma unroll
        for (int nt = 0; nt < 8; nt++)
#pragma unroll
            for (int r = 0; r < 4; r++) acc[mt][nt][r] = 0.f;

    const int nT = K / 16;

#define ISSUE(i)                                                      \
    do {                                                              \
        uint32_t _off = (uint32_t)((i) & 3) * STAGE_B;                \
        int _k0 = (i) * 16;                                           \
        cp_async16(aS[0] + _off, aG[0] + _k0);                        \
        cp_async16(aS[1] + _off, aG[1] + _k0);                        \
        cp_async16(aS[2] + _off, aG[2] + _k0);                        \
        cp_async16(aS[3] + _off, aG[3] + _k0);                        \
        cp_async16(bS[0] + _off, bG[0] + (size_t)_k0 * ldb);          \
        cp_async16(bS[1] + _off, bG[1] + (size_t)_k0 * ldb);          \
        cp_async16(bS[2] + _off, bG[2] + (size_t)_k0 * ldb);          \
        cp_async16(bS[3] + _off, bG[3] + (size_t)_k0 * ldb);          \
        asm volatile("cp.async.commit_group;");                       \
    } while (0)

    ISSUE(0);
    if (nT > 1) ISSUE(1);
    if (nT > 2) ISSUE(2);

    for (int i = 0; i < nT; i++) {
        const int rem = nT - 1 - i;  // groups issued after stage i
        if (rem >= 2)
            asm volatile("cp.async.wait_group 2;");
        else if (rem == 1)
            asm volatile("cp.async.wait_group 1;");
        else
            asm volatile("cp.async.wait_group 0;");
        __syncthreads();
        if (i + 3 < nT) ISSUE(i + 3);

        const uint32_t* Asb =
            (const uint32_t*)(smem + (size_t)(i & 3) * STAGE_B);
        const uint32_t* Bsb =
            (const uint32_t*)(smem + (size_t)(i & 3) * STAGE_B + A_STAGE_B);
#pragma unroll
        for (int kk = 0; kk < 16; kk += 8) {
            uint32_t a[4][4], b[8][2];
#pragma unroll
            for (int mt = 0; mt < 4; mt++) {
                int mrow = warpM * 64 + mt * 16;
                a[mt][0] = Asb[(mrow + g) * APADF + kk + t4];
                a[mt][1] = Asb[(mrow + g + 8) * APADF + kk + t4];
                a[mt][2] = Asb[(mrow + g) * APADF + kk + t4 + 4];
                a[mt][3] = Asb[(mrow + g + 8) * APADF + kk + t4 + 4];
            }
#pragma unroll
            for (int nt = 0; nt < 8; nt++) {
                int ncol = warpN * 64 + nt * 8;
                b[nt][0] = Bsb[(kk + t4) * BPADF + ncol + g];
                b[nt][1] = Bsb[(kk + t4 + 4) * BPADF + ncol + g];
            }
#pragma unroll
            for (int mt = 0; mt < 4; mt++)
#pragma unroll
                for (int nt = 0; nt < 8; nt++)
                    mma_tf32(acc[mt][nt], a[mt], b[nt]);
        }
    }
#undef ISSUE

    // epilogue
#pragma unroll
    for (int mt = 0; mt < 4; mt++) {
        int rBase = row0 + warpM * 64 + mt * 16 + g;
#pragma unroll
        for (int half = 0; half < 2; half++) {
            int r = rBase + half * 8;
            if (r >= mEff) continue;
            float* cp = C + (size_t)r * ldc;
#pragma unroll
            for (int nt = 0; nt < 8; nt++) {
                int col = col0 + warpN * 64 + nt * 8 + t4 * 2;
                cp[col] = acc[mt][nt][half * 2 + 0];
                cp[col + 1] = acc[mt][nt][half * 2 + 1];
            }
        }
    }
}

// ---------------- bulk tf32 rounding: 6 weight tensors in one launch ---------
__global__ void cvt6_kernel(const float4* s0, float4* d0, long long n0,
                            const float4* s1, float4* d1, long long n1,
                            const float4* s2, float4* d2, long long n2,
                            const float4* s3, float4* d3, long long n3,
                            const float4* s4, float4* d4, long long n4c,
                            const float4* s5, float4* d5, long long n5) {
    const float4* src;
    float4* dst;
    long long n;
    switch (blockIdx.y) {
        case 0: src = s0; dst = d0; n = n0; break;
        case 1: src = s1; dst = d1; n = n1; break;
        case 2: src = s2; dst = d2; n = n2; break;
        case 3: src = s3; dst = d3; n = n3; break;
        case 4: src = s4; dst = d4; n = n4c; break;
        default: src = s5; dst = d5; n = n5; break;
    }
    long long i = (long long)blockIdx.x * 256 + threadIdx.x;
    if (i < n) {
        float4 v = src[i];
        v.x = f2tf32f(v.x);
        v.y = f2tf32f(v.y);
        v.z = f2tf32f(v.z);
        v.w = f2tf32f(v.w);
        dst[i] = v;
    }
}

__global__ void cvt_kernel(const float4* __restrict__ src,
                           float4* __restrict__ dst, long long n4) {
    long long i = (long long)blockIdx.x * 256 + threadIdx.x;
    if (i < n4) {
        float4 v = src[i];
        v.x = f2tf32f(v.x);
        v.y = f2tf32f(v.y);
        v.z = f2tf32f(v.z);
        v.w = f2tf32f(v.w);
        dst[i] = v;
    }
}

// ---------------- RMSNorm ----------------
__global__ void rmsnorm_kernel(const float* __restrict__ x,
                               const float* __restrict__ w,
                               float* __restrict__ out) {
    const float* xr = x + (long long)blockIdx.x * H;
    float* orow = out + (long long)blockIdx.x * H;
    __shared__ float red[256];
    float s = 0.f;
    for (int j = threadIdx.x; j < H; j += 256) {
        float v = xr[j];
        s += v * v;
    }
    red[threadIdx.x] = s;
    __syncthreads();
    for (int st = 128; st > 0; st >>= 1) {
        if (threadIdx.x < st) red[threadIdx.x] += red[threadIdx.x + st];
        __syncthreads();
    }
    float inv = 1.0f / sqrtf(red[0] / (float)H + 1e-6f);
    for (int j = threadIdx.x; j < H; j += 256) orow[j] = w[j] * xr[j] * inv;
}

// ---------------- fp32 SGEMM (upstream of router) ----------------
__global__ __launch_bounds__(256, 2)
void sgemm_kernel(const float* __restrict__ A, int lda, long long sA,
                  const float* __restrict__ B, int ldb, long long sB,
                  float* __restrict__ C, int ldc, long long sC,
                  int K,
                  const float* __restrict__ bias,
                  const float* __restrict__ residual, int ldr,
                  int transB, int causal, int kLimit, float scale,
                  int selMode,
                  const float* B1, const float* B2,
                  const float* bias1, const float* bias2,
                  float* C1, float* C2) {
    __shared__ __align__(16) float As[2][8][128];
    __shared__ __align__(16) float Bs[2][8][128];

    const int bz = blockIdx.z;
    if (selMode) {
        if (bz == 1) { B = B1; bias = bias1; C = C1; }
        else if (bz == 2) { B = B2; bias = bias2; C = C2; }
    } else {
        A += (long long)bz * sA;
        B += (long long)bz * sB;
        C += (long long)bz * sC;
    }

    const int row0 = blockIdx.y * 128;
    const int col0 = blockIdx.x * 128;
    if (causal && col0 > row0) return;
    int Keff = kLimit ? min(K, row0 + 128) : K;

    const int tid = threadIdx.x;
    const int trow = (tid >> 4) * 8;
    const int tcol = (tid & 15) * 8;

    const int aRow = tid >> 1;
    const int aCol = (tid & 1) * 4;
    const int bRow = tid >> 5;
    const int bCol = (tid & 31) * 4;

    const float* Aptr = A + (long long)(row0 + aRow) * lda + aCol;
    const float* BptrNN = B + (long long)bRow * ldb + col0 + bCol;
    const float* BptrNT = B + (long long)(col0 + aRow) * ldb + aCol;

    unsigned long long acc[4][8];
#pragma unroll
    for (int i = 0; i < 4; i++)
#pragma unroll
        for (int j = 0; j < 8; j++) acc[i][j] = 0ull;

    float4 av = *reinterpret_cast<const float4*>(Aptr);
    float4 bv = transB ? *reinterpret_cast<const float4*>(BptrNT)
                       : *reinterpret_cast<const float4*>(BptrNN);
    As[0][aCol + 0][aRow] = av.x;
    As[0][aCol + 1][aRow] = av.y;
    As[0][aCol + 2][aRow] = av.z;
    As[0][aCol + 3][aRow] = av.w;
    if (transB) {
        Bs[0][aCol + 0][aRow] = bv.x;
        Bs[0][aCol + 1][aRow] = bv.y;
        Bs[0][aCol + 2][aRow] = bv.z;
        Bs[0][aCol + 3][aRow] = bv.w;
    } else {
        *reinterpret_cast<float4*>(&Bs[0][bRow][bCol]) = bv;
    }
    __syncthreads();

    int buf = 0;
    for (int k0 = 0; k0 < Keff; k0 += 8) {
        const bool more = (k0 + 8) < Keff;
        if (more) {
            av = *reinterpret_cast<const float4*>(Aptr + k0 + 8);
            bv = transB
                     ? *reinterpret_cast<const float4*>(BptrNT + k0 + 8)
                     : *reinterpret_cast<const float4*>(BptrNN + (long long)(k0 + 8) * ldb);
        }
#pragma unroll
        for (int kk = 0; kk < 8; kk++) {
            ulonglong2 a01 = *reinterpret_cast<const ulonglong2*>(&As[buf][kk][trow]);
            ulonglong2 a23 = *reinterpret_cast<const ulonglong2*>(&As[buf][kk][trow + 4]);
            float4 b0 = *reinterpret_cast<const float4*>(&Bs[buf][kk][tcol]);
            float4 b1 = *reinterpret_cast<const float4*>(&Bs[buf][kk][tcol + 4]);
            unsigned long long ap[4];
            ap[0] = a01.x; ap[1] = a01.y; ap[2] = a23.x; ap[3] = a23.y;
            float bvals[8];
            bvals[0] = b0.x; bvals[1] = b0.y; bvals[2] = b0.z; bvals[3] = b0.w;
            bvals[4] = b1.x; bvals[5] = b1.y; bvals[6] = b1.z; bvals[7] = b1.w;
#pragma unroll
            for (int j = 0; j < 8; j++) {
                unsigned long long bp;
                asm("mov.b64 %0, {%1, %1};" : "=l"(bp) : "f"(bvals[j]));
#pragma unroll
                for (int i2 = 0; i2 < 4; i2++) {
                    asm("fma.rn.f32x2 %0, %1, %2, %0;"
                        : "+l"(acc[i2][j]) : "l"(ap[i2]), "l"(bp));
                }
            }
        }
        if (more) {
            int nb = buf ^ 1;
            As[nb][aCol + 0][aRow] = av.x;
            As[nb][aCol + 1][aRow] = av.y;
            As[nb][aCol + 2][aRow] = av.z;
            As[nb][aCol + 3][aRow] = av.w;
            if (transB) {
                Bs[nb][aCol + 0][aRow] = bv.x;
                Bs[nb][aCol + 1][aRow] = bv.y;
                Bs[nb][aCol + 2][aRow] = bv.z;
                Bs[nb][aCol + 3][aRow] = bv.w;
            } else {
                *reinterpret_cast<float4*>(&Bs[nb][bRow][bCol]) = bv;
            }
        }
        __syncthreads();
        buf ^= 1;
    }

#pragma unroll
    for (int i2 = 0; i2 < 4; i2++) {
#pragma unroll
        for (int j = 0; j < 8; j++) {
            float lo, hi;
            asm("mov.b64 {%0, %1}, %2;" : "=f"(lo), "=f"(hi) : "l"(acc[i2][j]));
            int c = col0 + tcol + j;
#pragma unroll
            for (int half = 0; half < 2; half++) {
                int r = row0 + trow + 2 * i2 + half;
                float v = (half == 0 ? lo : hi) * scale;
                if (bias) v += bias[c];
                if (residual) v += residual[(long long)r * ldr + c];
                C[(long long)r * ldc + c] = v;
            }
        }
    }
}

// ---------------- RoPE ----------------
__global__ void rope_kernel(float* __restrict__ q, float* __restrict__ k) {
    int s = blockIdx.x;
    int h = blockIdx.y;
    int j = threadIdx.x;
    double invd = pow(1.0e6, -(double)j / 64.0);
    float ang = (float)((double)s * invd);
    float c = cosf(ang), sn = sinf(ang);
    long long base = ((long long)s * NH + h) * D;
    float q1 = q[base + j], q2 = q[base + j + 64];
    q[base + j] = q1 * c - q2 * sn;
    q[base + j + 64] = q2 * c + q1 * sn;
    float k1 = k[base + j], k2 = k[base + j + 64];
    k[base + j] = k1 * c - k2 * sn;
    k[base + j + 64] = k2 * c + k1 * sn;
}

// ---------------- causal row softmax ----------------
__global__ void softmax_kernel(float* __restrict__ scores) {
    int r = blockIdx.x;
    float* row = scores + ((long long)blockIdx.y * S + r) * S;
    const int limit = r + 1;
    const int rBlk = ((r >> 7) + 1) << 7;
    __shared__ float red[256];
    int tid = threadIdx.x;
    float m = -FLT_MAX;
    for (int j = tid; j < limit; j += 256) m = fmaxf(m, row[j]);
    red[tid] = m;
    __syncthreads();
    for (int st = 128; st > 0; st >>= 1) {
        if (tid < st) red[tid] = fmaxf(red[tid], red[tid + st]);
        __syncthreads();
    }
    m = red[0];
    __syncthreads();
    float sum = 0.f;
    for (int j = tid; j < limit; j += 256) {
        float e = expf(row[j] - m);
        row[j] = e;
        sum += e;
    }
    red[tid] = sum;
    __syncthreads();
    for (int st = 128; st > 0; st >>= 1) {
        if (tid < st) red[tid] += red[tid + st];
        __syncthreads();
    }
    float inv = 1.0f / red[0];
    for (int j = tid; j < limit; j += 256) row[j] *= inv;
    for (int j = limit + tid; j < rBlk; j += 256) row[j] = 0.f;
}

// ---------------- router ----------------
__global__ void router_kernel(const float* __restrict__ h2,
                              const float* __restrict__ gate_w,
                              float* __restrict__ logits_out,
                              int* __restrict__ idxbuf,
                              int* __restrict__ cnt,
                              int* __restrict__ tokmap,
                              float* __restrict__ tokw) {
    int s = blockIdx.x;
    const float* hr = h2 + (long long)s * H;
    __shared__ float red[256][E];
    float p[E];
#pragma unroll
    for (int e = 0; e < E; e++) p[e] = 0.f;
    for (int j = threadIdx.x; j < H; j += 256) {
        float hv = hr[j];
#pragma unroll
        for (int e = 0; e < E; e++) p[e] += hv * gate_w[j * E + e];
    }
#pragma unroll
    for (int e = 0; e < E; e++) red[threadIdx.x][e] = p[e];
    __syncthreads();
    for (int st = 128; st > 0; st >>= 1) {
        if (threadIdx.x < st)
#pragma unroll
            for (int e = 0; e < E; e++) red[threadIdx.x][e] += red[threadIdx.x + st][e];
        __syncthreads();
    }
    if (threadIdx.x == 0) {
        float logit[E];
        float m = -FLT_MAX;
#pragma unroll
        for (int e = 0; e < E; e++) {
            logit[e] = red[0][e];
            logits_out[(long long)s * E + e] = logit[e];
            m = fmaxf(m, logit[e]);
        }
        float sum = 0.f, rw[E];
#pragma unroll
        for (int e = 0; e < E; e++) {
            rw[e] = expf(logit[e] - m);
            sum += rw[e];
        }
        float inv = 1.0f / sum;
#pragma unroll
        for (int e = 0; e < E; e++) rw[e] *= inv;
        bool used[E];
#pragma unroll
        for (int e = 0; e < E; e++) used[e] = false;
        for (int k = 0; k < TOPK; k++) {
            int best = -1;
            float bvv = -FLT_MAX;
            for (int e = 0; e < E; e++)
                if (!used[e] && rw[e] > bvv) { bvv = rw[e]; best = e; }
            used[best] = true;
            int pos = atomicAdd(&cnt[best], 1);
            idxbuf[best * S + pos] = s;
            tokmap[s * TOPK + k] = best * S + pos;
            tokw[s * TOPK + k] = bvv;
        }
    }
}

// ---------------- h2 . sgate ----------------
__global__ void rowdot_kernel(const float* __restrict__ h2,
                              const float* __restrict__ sgate,
                              float* __restrict__ gatev) {
    int s = blockIdx.x;
    const float* hr = h2 + (long long)s * H;
    __shared__ float red[256];
    float acc = 0.f;
    for (int j = threadIdx.x; j < H; j += 256) acc += hr[j] * sgate[j];
    red[threadIdx.x] = acc;
    __syncthreads();
    for (int st = 128; st > 0; st >>= 1) {
        if (threadIdx.x < st) red[threadIdx.x] += red[threadIdx.x + st];
        __syncthreads();
    }
    if (threadIdx.x == 0) gatev[s] = red[0];
}

// ---------------- silu(g)*u, experts (output tf32-rounded) ----------------
__global__ void silu_mul_expert_kernel(float* __restrict__ gb,
                                       const float* __restrict__ ub,
                                       const int* __restrict__ cnt) {
    int e = blockIdx.y;
    long long i = (long long)blockIdx.x * 256 + threadIdx.x;
    long long lim = (long long)cnt[e] * IE;
    if (i >= lim) return;
    size_t o = (size_t)e * S * IE + i;
    float x = gb[o];
    float sg = 1.0f / (1.0f + expf(-x));
    gb[o] = f2tf32f(x * sg * ub[o]);
}

// ---------------- silu(g)*u shared (output tf32-rounded) ----------------
__global__ void silu_mul_kernel(float* __restrict__ g, const float* __restrict__ u,
                                long long n) {
    long long i = (long long)blockIdx.x * 256 + threadIdx.x;
    if (i < n) {
        float x = g[i];
        float sg = 1.0f / (1.0f + expf(-x));
        g[i] = f2tf32f(x * sg * u[i]);
    }
}

// ---------------- final combine ----------------
__global__ void final_kernel(const float* __restrict__ x1,
                             const float* __restrict__ eo,
                             const int* __restrict__ tokmap,
                             const float* __restrict__ tokw,
                             const float* __restrict__ sdwn,
                             const float* __restrict__ gatev,
                             float* __restrict__ out) {
    long long i = (long long)blockIdx.x * 256 + threadIdx.x;
    int s = (int)(i / H);
    int c = (int)(i % H);
    float gv = 1.0f / (1.0f + expf(-gatev[s]));
    float acc = x1[i] + gv * sdwn[i];
#pragma unroll
    for (int j = 0; j < TOPK; j++) {
        int row = tokmap[s * TOPK + j];
        acc += tokw[s * TOPK + j] * eo[(size_t)row * H + c];
    }
    out[i] = acc;
}

// ---------------- host ----------------
static void launch_mma(const float* A, int lda, long long aStrE,
                       const float* B0, const float* B1, int ldb, long long bStrE,
                       float* C0, float* C1, int ldc, long long cStrE,
                       int M, int N, int K,
                       const int* gidx, int gstr, const int* cnt, int eShift,
                       int nz) {
    dim3 grid(N / 128, (M + 127) / 128, nz);
    mma_gemm_kernel<<<grid, 128, MMA_SMEM>>>(A, lda, aStrE, B0, B1, ldb, bStrE,
                                             C0, C1, ldc, cStrE, M, N, K,
                                             gidx, gstr, cnt, eShift);
}

extern "C" void kernel_launch(void* const* d_in, const int* in_sizes, int n_in,
                              void* d_out, int out_size) {
    (void)in_sizes; (void)n_in; (void)out_size;
    const float* x     = (const float*)d_in[0];
    const float* ln1   = (const float*)d_in[1];
    const float* ln2   = (const float*)d_in[2];
    const float* wq    = (const float*)d_in[3];
    const float* bq    = (const float*)d_in[4];
    const float* wk    = (const float*)d_in[5];
    const float* bk    = (const float*)d_in[6];
    const float* wv    = (const float*)d_in[7];
    const float* bv    = (const float*)d_in[8];
    const float* wo    = (const float*)d_in[9];
    const float* gatew = (const float*)d_in[10];
    const float* eg    = (const float*)d_in[11];
    const float* eu    = (const float*)d_in[12];
    const float* ed    = (const float*)d_in[13];
    const float* sg    = (const float*)d_in[14];
    const float* su    = (const float*)d_in[15];
    const float* sd    = (const float*)d_in[16];
    const float* sgate = (const float*)d_in[17];
    float* out = (float*)d_out;

    cudaFuncSetAttribute(mma_gemm_kernel,
                         cudaFuncAttributeMaxDynamicSharedMemorySize, MMA_SMEM);

    float *h, *q, *k, *v, *scores, *attn, *x1, *h2, *ch2, *gb, *ub, *eo, *sgb,
        *sub, *sdwn, *gatev, *tokw;
    float *ceg, *ceu, *ced, *csg, *csu, *csd;
    int *idx, *cnt, *tokmap;
    cudaGetSymbolAddress((void**)&h, g_h);
    cudaGetSymbolAddress((void**)&q, g_q);
    cudaGetSymbolAddress((void**)&k, g_k);
    cudaGetSymbolAddress((void**)&v, g_v);
    cudaGetSymbolAddress((void**)&scores, g_scores);
    cudaGetSymbolAddress((void**)&attn, g_attn);
    cudaGetSymbolAddress((void**)&x1, g_x1);
    cudaGetSymbolAddress((void**)&h2, g_h2);
    cudaGetSymbolAddress((void**)&ch2, g_ch2);
    cudaGetSymbolAddress((void**)&gb, g_gb);
    cudaGetSymbolAddress((void**)&ub, g_ub);
    cudaGetSymbolAddress((void**)&eo, g_eo);
    cudaGetSymbolAddress((void**)&sgb, g_sgb);
    cudaGetSymbolAddress((void**)&sub, g_sub);
    cudaGetSymbolAddress((void**)&sdwn, g_sdwn);
    cudaGetSymbolAddress((void**)&gatev, g_gatev);
    cudaGetSymbolAddress((void**)&idx, g_idx);
    cudaGetSymbolAddress((void**)&cnt, g_cnt);
    cudaGetSymbolAddress((void**)&tokmap, g_tokmap);
    cudaGetSymbolAddress((void**)&tokw, g_tokw);
    cudaGetSymbolAddress((void**)&ceg, g_ceg);
    cudaGetSymbolAddress((void**)&ceu, g_ceu);
    cudaGetSymbolAddress((void**)&ced, g_ced);
    cudaGetSymbolAddress((void**)&csg, g_csg);
    cudaGetSymbolAddress((void**)&csu, g_csu);
    cudaGetSymbolAddress((void**)&csd, g_csd);

    const float ascale = 0.08838834764831845f;

    // 0. pre-round all MoE/shared weights to tf32 in ONE launch
    {
        long long nEG = (long long)E * H * IE / 4;
        long long nED = (long long)E * IE * H / 4;
        long long nSG = (long long)H * IS / 4;
        long long nSD = (long long)IS * H / 4;
        unsigned gx = (unsigned)((nEG + 255) / 256);
        dim3 grid(gx, 6);
        cvt6_kernel<<<grid, 256>>>((const float4*)eg, (float4*)ceg, nEG,
                                   (const float4*)eu, (float4*)ceu, nEG,
                                   (const float4*)ed, (float4*)ced, nED,
                                   (const float4*)sg, (float4*)csg, nSG,
                                   (const float4*)su, (float4*)csu, nSG,
                                   (const float4*)sd, (float4*)csd, nSD);
    }

    // 1. h = rmsnorm(x, ln1)
    rmsnorm_kernel<<<S, 256>>>(x, ln1, h);

    // 2. q,k,v (batched fp32)
    {
        dim3 grid((NH * D) / 128, S / 128, 3);
        sgemm_kernel<<<grid, 256>>>(h, H, 0, wq, NH * D, 0, q, NH * D, 0, H,
                                    bq, nullptr, 0, 0, 0, 0, 1.0f,
                                    1, wk, wv, bk, bv, k, v);
    }

    // 3. RoPE
    rope_kernel<<<dim3(S, NH), 64>>>(q, k);

    // 4. scores
    {
        dim3 grid(S / 128, S / 128, NH);
        sgemm_kernel<<<grid, 256>>>(q, NH * D, D, k, NH * D, D, scores, S,
                                    (long long)S * S, D, nullptr, nullptr, 0,
                                    1, 1, 0, ascale,
                                    0, nullptr, nullptr, nullptr, nullptr,
                                    nullptr, nullptr);
    }

    // 5. softmax
    softmax_kernel<<<dim3(S, NH), 256>>>(scores);

    // 6. attn = probs @ v
    {
        dim3 grid(D / 128, S / 128, NH);
        sgemm_kernel<<<grid, 256>>>(scores, S, (long long)S * S, v, NH * D, D,
                                    attn, NH * D, D, S, nullptr, nullptr, 0,
                                    0, 0, 1, 1.0f,
                                    0, nullptr, nullptr, nullptr, nullptr,
                                    nullptr, nullptr);
    }

    // 7. x1 = x + attn @ wo
    {
        dim3 grid(H / 128, S / 128, 1);
        sgemm_kernel<<<grid, 256>>>(attn, NH * D, 0, wo, H, 0, x1, H, 0,
                                    NH * D, nullptr, x, H, 0, 0, 0, 1.0f,
                                    0, nullptr, nullptr, nullptr, nullptr,
                                    nullptr, nullptr);
    }

    // 8. h2 = rmsnorm(x1, ln2); tf32 copy for MoE A
    rmsnorm_kernel<<<S, 256>>>(x1, ln2, h2);
    {
        long long n4 = (long long)S * H / 4;
        cvt_kernel<<<(unsigned)((n4 + 255) / 256), 256>>>((const float4*)h2,
                                                          (float4*)ch2, n4);
    }

    // 9. router (exact h2)
    cudaMemsetAsync(cnt, 0, E * sizeof(int));
    router_kernel<<<S, 256>>>(h2, gatew, out + (long long)S * H, idx, cnt,
                              tokmap, tokw);

    // 10. MoE gate+up (z = 2E)
    launch_mma(ch2, H, 0, ceg, ceu, IE, (long long)H * IE,
               gb, ub, IE, (long long)S * IE, S, IE, H, idx, S, cnt, 1, 2 * E);

    // 11. silu (+tf32 round)
    {
        dim3 grid((unsigned)(((long long)S * IE + 255) / 256), E);
        silu_mul_expert_kernel<<<grid, 256>>>(gb, ub, cnt);
    }

    // 12. MoE down (z = E)
    launch_mma(gb, IE, (long long)S * IE, ced, nullptr, H, (long long)IE * H,
               eo, nullptr, H, (long long)S * H, S, H, IE, nullptr, 0, cnt, 0, E);

    // 13. shared expert
    launch_mma(ch2, H, 0, csg, csu, IS, 0, sgb, sub, IS, 0, S, IS, H,
               nullptr, 0, nullptr, 1, 2);
    {
        long long n = (long long)S * IS;
        silu_mul_kernel<<<(unsigned)((n + 255) / 256), 256>>>(sgb, sub, n);
    }
    launch_mma(sgb, IS, 0, csd, nullptr, H, 0, sdwn, nullptr, H, 0, S, H, IS,
               nullptr, 0, nullptr, 0, 1);

    // 14. gate scalar
    rowdot_kernel<<<S, 256>>>(h2, sgate, gatev);

    // 15. combine
    final_kernel<<<(S * H) / 256, 256>>>(x1, eo, tokmap, tokw, sdwn, gatev, out);
}